// round 2
// baseline (speedup 1.0000x reference)
#include <cuda_runtime.h>
#include <math.h>

// ---------------------------------------------------------------------------
// DLRM forward: bottom MLP -> embedding gather + pairwise interaction -> top MLP
// B=4096, M_DEN=13, N_EMB=26, EMB_DIM=64, NI=27, N_PAIRS=351
// LN_BOT: 13 -> 512 -> 256 -> 64
// LN_TOP: 415 -> 512 -> 256 -> 1
// ---------------------------------------------------------------------------

#define BATCH   4096
#define MDEN    13
#define NEMB    26
#define NI      27
#define NPAIRS  351
#define EMBD    64
#define VOCAB   100000
#define TOPIN   (NPAIRS + EMBD)   // 415

// Scratch layout (floats) in one __device__ global array
#define OFF_H1  0                              // [4096,512] bottom layer0 out
#define OFF_H2  (OFF_H1 + BATCH*512)           // [4096,256] bottom layer1 out
#define OFF_XB  (OFF_H2 + BATCH*256)           // [4096, 64] bottom out
#define OFF_P   (OFF_XB + BATCH*EMBD)          // [4096,415] top MLP input
#define OFF_T1  (OFF_P  + BATCH*TOPIN)         // [4096,512] top layer0 out
#define OFF_T2  (OFF_T1 + BATCH*512)           // [4096,256] top layer1 out
#define SCRATCH_TOTAL (OFF_T2 + BATCH*256)

__device__ __align__(16) float g_scratch[SCRATCH_TOTAL];

// ---------------------------------------------------------------------------
// Tiled SGEMM: C[M,N] = act(A)[M,K] @ W[N,K]^T + bias[N]
//   A row-major [M,K]  (optionally from scratch via aoff)
//   W row-major [N,K]  (PyTorch linear layout)
//   ReLU (if RELU) applied to A elements on load.
// M % BM == 0 and N % BN == 0 are guaranteed by the launch configs below.
// K is arbitrary (guarded).
// ---------------------------------------------------------------------------
template<int BM, int BN, int BK, int TM, int TN, bool RELU>
__global__ __launch_bounds__((BM/TM)*(BN/TN))
void gemm_kernel(const float* __restrict__ Aext, int aoff,
                 const float* __restrict__ W,
                 const float* __restrict__ bias,
                 int coff, int M, int N, int K)
{
    constexpr int THREADS = (BM/TM)*(BN/TN);
    __shared__ float As[BK][BM + 4];
    __shared__ float Ws[BK][BN + 4];

    const float* A = Aext ? Aext : (const float*)g_scratch + aoff;
    float* C = g_scratch + coff;

    const int tid = threadIdx.x;
    const int tx  = tid % (BN/TN);   // n-dim
    const int ty  = tid / (BN/TN);   // m-dim
    const int m0  = blockIdx.y * BM;
    const int n0  = blockIdx.x * BN;

    float acc[TM][TN];
    #pragma unroll
    for (int i = 0; i < TM; i++)
        #pragma unroll
        for (int j = 0; j < TN; j++)
            acc[i][j] = 0.f;

    for (int k0 = 0; k0 < K; k0 += BK) {
        // Load A tile (transposed into SMEM), ReLU fused
        #pragma unroll 4
        for (int e = tid; e < BM*BK; e += THREADS) {
            int m = e / BK, k = e % BK;
            float v = 0.f;
            if (k0 + k < K) v = A[(size_t)(m0 + m) * K + k0 + k];
            if (RELU) v = fmaxf(v, 0.f);
            As[k][m] = v;
        }
        // Load W tile (transposed into SMEM)
        #pragma unroll 4
        for (int e = tid; e < BN*BK; e += THREADS) {
            int n = e / BK, k = e % BK;
            float v = 0.f;
            if (k0 + k < K) v = W[(size_t)(n0 + n) * K + k0 + k];
            Ws[k][n] = v;
        }
        __syncthreads();

        #pragma unroll
        for (int k = 0; k < BK; k++) {
            float ra[TM], rw[TN];
            #pragma unroll
            for (int i = 0; i < TM; i += 4) {
                float4 t = *(const float4*)&As[k][ty*TM + i];
                ra[i] = t.x; ra[i+1] = t.y; ra[i+2] = t.z; ra[i+3] = t.w;
            }
            #pragma unroll
            for (int j = 0; j < TN; j += 4) {
                float4 t = *(const float4*)&Ws[k][tx*TN + j];
                rw[j] = t.x; rw[j+1] = t.y; rw[j+2] = t.z; rw[j+3] = t.w;
            }
            #pragma unroll
            for (int i = 0; i < TM; i++)
                #pragma unroll
                for (int j = 0; j < TN; j++)
                    acc[i][j] += ra[i] * rw[j];
        }
        __syncthreads();
    }

    // Epilogue: add bias, store
    #pragma unroll
    for (int i = 0; i < TM; i++) {
        int m = m0 + ty*TM + i;
        #pragma unroll
        for (int j = 0; j < TN; j++) {
            int n = n0 + tx*TN + j;
            C[(size_t)m * N + n] = acc[i][j] + bias[n];
        }
    }
}

// ---------------------------------------------------------------------------
// Interaction kernel (fuses the embedding gather):
//   per batch row b:
//     T[0]      = x_bot[b]                     (64 floats)
//     T[1+f]    = emb[f, sparse_idx[f,b], :]   (f = 0..25)
//     P[b][0:64]      = x_bot[b]
//     P[b][64 + p]    = dot(T[i], T[j]) for lower-triangle pairs (i>j),
//                       row-major tril order.
// One block (128 threads) per batch row.
// NOTE: sparse_idx is int32 (JAX x64 is disabled by default, so the declared
// int64 is materialized as int32).
// ---------------------------------------------------------------------------
__global__ __launch_bounds__(128)
void interact_kernel(const int* __restrict__ sidx,
                     const float* __restrict__ emb)
{
    __shared__ float T[NI][EMBD];

    const int b    = blockIdx.x;
    const int tid  = threadIdx.x;
    const int wid  = tid >> 5;
    const int lane = tid & 31;

    const float* xbot = g_scratch + OFF_XB + (size_t)b * EMBD;

    // Gather 27 rows of 64 floats into SMEM (one warp per row, round-robin)
    for (int r = wid; r < NI; r += 4) {
        const float* src;
        if (r == 0) {
            src = xbot;
        } else {
            int ix = sidx[(size_t)(r - 1) * BATCH + b];
            // defensive clamp: never fault even if dtype assumption is wrong
            ix = ix < 0 ? 0 : (ix >= VOCAB ? VOCAB - 1 : ix);
            src = emb + ((size_t)(r - 1) * VOCAB + (size_t)ix) * EMBD;
        }
        float2 v = ((const float2*)src)[lane];
        ((float2*)T[r])[lane] = v;
    }
    __syncthreads();

    float* prow = g_scratch + OFF_P + (size_t)b * TOPIN;

    // P[b][0:64] = x_bot[b]
    if (tid < 32) {
        float2 v = ((const float2*)T[0])[tid];
        prow[2*tid]     = v.x;
        prow[2*tid + 1] = v.y;
    }

    // 351 lower-triangle pair dot products
    for (int p = tid; p < NPAIRS; p += 128) {
        // largest i with i*(i-1)/2 <= p
        int i = (int)((1.0f + sqrtf(1.0f + 8.0f * (float)p)) * 0.5f);
        while (i * (i - 1) / 2 > p) i--;
        while ((i + 1) * i / 2 <= p) i++;
        int j = p - i * (i - 1) / 2;

        const float4* Ti = (const float4*)T[i];
        const float4* Tj = (const float4*)T[j];
        float s = 0.f;
        #pragma unroll
        for (int d = 0; d < EMBD/4; d++) {
            float4 a = Ti[d], c = Tj[d];
            s += a.x*c.x + a.y*c.y + a.z*c.z + a.w*c.w;
        }
        prow[EMBD + p] = s;
    }
}

// ---------------------------------------------------------------------------
// Final layer: out[b] = dot(relu(t2[b]), tw2) + tb2   (N=1)
// One warp per batch row.
// ---------------------------------------------------------------------------
__global__ __launch_bounds__(128)
void final_kernel(const float* __restrict__ w,
                  const float* __restrict__ bias,
                  float* __restrict__ out)
{
    const int warp = blockIdx.x * 4 + (threadIdx.x >> 5);
    const int lane = threadIdx.x & 31;
    if (warp >= BATCH) return;

    const float* row = g_scratch + OFF_T2 + (size_t)warp * 256;
    float s = 0.f;
    #pragma unroll
    for (int d = lane; d < 256; d += 32) {
        float v = fmaxf(row[d], 0.f);
        s += v * w[d];
    }
    #pragma unroll
    for (int o = 16; o; o >>= 1) s += __shfl_xor_sync(0xffffffffu, s, o);
    if (lane == 0) out[warp] = s + bias[0];
}

// ---------------------------------------------------------------------------
// Launch sequence
// ---------------------------------------------------------------------------
extern "C" void kernel_launch(void* const* d_in, const int* in_sizes, int n_in,
                              void* d_out, int out_size)
{
    const float* dense_x = (const float*)d_in[0];
    const int*   sidx    = (const int*)d_in[1];
    const float* emb     = (const float*)d_in[2];
    const float* bw0 = (const float*)d_in[3];
    const float* bb0 = (const float*)d_in[4];
    const float* bw1 = (const float*)d_in[5];
    const float* bb1 = (const float*)d_in[6];
    const float* bw2 = (const float*)d_in[7];
    const float* bb2 = (const float*)d_in[8];
    const float* tw0 = (const float*)d_in[9];
    const float* tb0 = (const float*)d_in[10];
    const float* tw1 = (const float*)d_in[11];
    const float* tb1 = (const float*)d_in[12];
    const float* tw2 = (const float*)d_in[13];
    const float* tb2 = (const float*)d_in[14];
    float* out = (float*)d_out;

    // Bottom MLP
    // L0: [4096,13] -> [4096,512], no relu on input
    {
        dim3 grid(512/64, BATCH/128);
        gemm_kernel<128,64,16,8,4,false><<<grid, 256>>>(dense_x, 0, bw0, bb0,
                                                        OFF_H1, BATCH, 512, MDEN);
    }
    // L1: relu(h1) -> [4096,256]
    {
        dim3 grid(256/64, BATCH/128);
        gemm_kernel<128,64,16,8,4,true><<<grid, 256>>>(nullptr, OFF_H1, bw1, bb1,
                                                       OFF_H2, BATCH, 256, 512);
    }
    // L2: relu(h2) -> [4096,64]
    {
        dim3 grid(64/64, BATCH/64);
        gemm_kernel<64,64,16,4,4,true><<<grid, 256>>>(nullptr, OFF_H2, bw2, bb2,
                                                      OFF_XB, BATCH, 64, 256);
    }

    // Embedding gather + pairwise interaction -> P [4096,415]
    interact_kernel<<<BATCH, 128>>>(sidx, emb);

    // Top MLP
    // L0: [4096,415] -> [4096,512], no relu on input
    {
        dim3 grid(512/64, BATCH/128);
        gemm_kernel<128,64,16,8,4,false><<<grid, 256>>>(nullptr, OFF_P, tw0, tb0,
                                                        OFF_T1, BATCH, 512, TOPIN);
    }
    // L1: relu(t1) -> [4096,256]
    {
        dim3 grid(256/64, BATCH/128);
        gemm_kernel<128,64,16,8,4,true><<<grid, 256>>>(nullptr, OFF_T1, tw1, tb1,
                                                       OFF_T2, BATCH, 256, 512);
    }
    // L2: relu(t2) -> [4096,1]
    final_kernel<<<BATCH/4, 128>>>(tw2, tb2, out);
}

// round 3
// speedup vs baseline: 1.2401x; 1.2401x over previous
#include <cuda_runtime.h>
#include <math.h>

// ---------------------------------------------------------------------------
// DLRM forward: bottom MLP -> embedding gather + pairwise interaction -> top MLP
// B=4096, M_DEN=13, N_EMB=26, EMB_DIM=64, NI=27, N_PAIRS=351
// LN_BOT: 13 -> 512 -> 256 -> 64
// LN_TOP: 415 -> 512 -> 256 -> 1
// ---------------------------------------------------------------------------

#define BATCH   4096
#define MDEN    13
#define NEMB    26
#define NI      27
#define NPAIRS  351
#define EMBD    64
#define VOCAB   100000
#define TOPIN   (NPAIRS + EMBD)   // 415

// Scratch layout (floats) in one __device__ global array
#define OFF_H1  0                              // [4096,512] bottom layer0 out
#define OFF_H2  (OFF_H1 + BATCH*512)           // [4096,256] bottom layer1 out
#define OFF_XB  (OFF_H2 + BATCH*256)           // [4096, 64] bottom out
#define OFF_P   (OFF_XB + BATCH*EMBD)          // [4096,415] top MLP input
#define OFF_T1  (OFF_P  + BATCH*TOPIN)         // [4096,512] top layer0 out
#define OFF_T2  (OFF_T1 + BATCH*512)           // [4096,256] top layer1 out
#define SCRATCH_TOTAL (OFF_T2 + BATCH*256)

__device__ __align__(16) float g_scratch[SCRATCH_TOTAL];

// ---------------------------------------------------------------------------
// Tiled SGEMM: C[M,N] = act(A)[M,K] @ W[N,K]^T + bias[N]
// ---------------------------------------------------------------------------
template<int BM, int BN, int BK, int TM, int TN, bool RELU>
__global__ __launch_bounds__((BM/TM)*(BN/TN))
void gemm_kernel(const float* __restrict__ Aext, int aoff,
                 const float* __restrict__ W,
                 const float* __restrict__ bias,
                 int coff, int M, int N, int K)
{
    constexpr int THREADS = (BM/TM)*(BN/TN);
    __shared__ float As[BK][BM + 4];
    __shared__ float Ws[BK][BN + 4];

    const float* A = Aext ? Aext : (const float*)g_scratch + aoff;
    float* C = g_scratch + coff;

    const int tid = threadIdx.x;
    const int tx  = tid % (BN/TN);   // n-dim
    const int ty  = tid / (BN/TN);   // m-dim
    const int m0  = blockIdx.y * BM;
    const int n0  = blockIdx.x * BN;

    float acc[TM][TN];
    #pragma unroll
    for (int i = 0; i < TM; i++)
        #pragma unroll
        for (int j = 0; j < TN; j++)
            acc[i][j] = 0.f;

    for (int k0 = 0; k0 < K; k0 += BK) {
        #pragma unroll 4
        for (int e = tid; e < BM*BK; e += THREADS) {
            int m = e / BK, k = e % BK;
            float v = 0.f;
            if (k0 + k < K) v = A[(size_t)(m0 + m) * K + k0 + k];
            if (RELU) v = fmaxf(v, 0.f);
            As[k][m] = v;
        }
        #pragma unroll 4
        for (int e = tid; e < BN*BK; e += THREADS) {
            int n = e / BK, k = e % BK;
            float v = 0.f;
            if (k0 + k < K) v = W[(size_t)(n0 + n) * K + k0 + k];
            Ws[k][n] = v;
        }
        __syncthreads();

        #pragma unroll
        for (int k = 0; k < BK; k++) {
            float ra[TM], rw[TN];
            #pragma unroll
            for (int i = 0; i < TM; i += 4) {
                float4 t = *(const float4*)&As[k][ty*TM + i];
                ra[i] = t.x; ra[i+1] = t.y; ra[i+2] = t.z; ra[i+3] = t.w;
            }
            #pragma unroll
            for (int j = 0; j < TN; j += 4) {
                float4 t = *(const float4*)&Ws[k][tx*TN + j];
                rw[j] = t.x; rw[j+1] = t.y; rw[j+2] = t.z; rw[j+3] = t.w;
            }
            #pragma unroll
            for (int i = 0; i < TM; i++)
                #pragma unroll
                for (int j = 0; j < TN; j++)
                    acc[i][j] += ra[i] * rw[j];
        }
        __syncthreads();
    }

    #pragma unroll
    for (int i = 0; i < TM; i++) {
        int m = m0 + ty*TM + i;
        #pragma unroll
        for (int j = 0; j < TN; j++) {
            int n = n0 + tx*TN + j;
            C[(size_t)m * N + n] = acc[i][j] + bias[n];
        }
    }
}

// ---------------------------------------------------------------------------
// Interaction kernel, register-tiled.
//   One WARP per batch row (4 warps / block).
//   T (27x64) stored k-major in SMEM: Tt[k][r], r padded to 36 for alignment.
//   28 lanes each compute a 4x4 tile of the 28x28 (padded) Gram matrix:
//   lane t -> (ti, tj) with ti >= tj covers the lower triangle.
//   Per k-step: 2x float4 LDS feeding 16 FMAs (4x fewer SMEM bytes/FLOP
//   than the pair-dot formulation).
// ---------------------------------------------------------------------------
#define IPAD 36

__global__ __launch_bounds__(128)
void interact_kernel(const int* __restrict__ sidx,
                     const float* __restrict__ emb)
{
    __shared__ __align__(16) float Tt[4][EMBD][IPAD];

    const int w    = threadIdx.x >> 5;
    const int lane = threadIdx.x & 31;
    const int b    = blockIdx.x * 4 + w;

    const float* xbot = g_scratch + OFF_XB + (size_t)b * EMBD;
    float (*T)[IPAD] = Tt[w];

    // Gather: 27 source rows of 64 floats; each lane loads one float2 per row
    // (coalesced 256B global read) and scatters it transposed into SMEM.
    #pragma unroll 1
    for (int r = 0; r < NI; r++) {
        const float* src;
        if (r == 0) {
            src = xbot;
        } else {
            int ix = sidx[(size_t)(r - 1) * BATCH + b];
            ix = ix < 0 ? 0 : (ix >= VOCAB ? VOCAB - 1 : ix);
            src = emb + ((size_t)(r - 1) * VOCAB + (size_t)ix) * EMBD;
        }
        float2 v = ((const float2*)src)[lane];
        T[2*lane    ][r] = v.x;
        T[2*lane + 1][r] = v.y;
    }
    __syncwarp();

    float* prow = g_scratch + OFF_P + (size_t)b * TOPIN;

    // P[b][0:64] = x_bot[b]
    {
        float2 v = ((const float2*)xbot)[lane];
        prow[2*lane]     = v.x;
        prow[2*lane + 1] = v.y;
    }

    if (lane < 28) {
        // lane -> lower-triangle 4x4 tile (ti, tj), ti in 0..6, tj <= ti
        int ti = 0;
        while ((ti + 1) * (ti + 2) / 2 <= lane) ti++;
        int tj = lane - ti * (ti + 1) / 2;

        float acc[4][4];
        #pragma unroll
        for (int a = 0; a < 4; a++)
            #pragma unroll
            for (int c = 0; c < 4; c++)
                acc[a][c] = 0.f;

        #pragma unroll 8
        for (int k = 0; k < EMBD; k++) {
            float4 av = *(const float4*)&T[k][4*ti];
            float4 bv = *(const float4*)&T[k][4*tj];
            float ra[4] = {av.x, av.y, av.z, av.w};
            float rb[4] = {bv.x, bv.y, bv.z, bv.w};
            #pragma unroll
            for (int a = 0; a < 4; a++)
                #pragma unroll
                for (int c = 0; c < 4; c++)
                    acc[a][c] += ra[a] * rb[c];
        }

        // Scatter the valid lower-triangle entries: pair index p = i(i-1)/2 + j
        #pragma unroll
        for (int a = 0; a < 4; a++) {
            int i = 4*ti + a;
            #pragma unroll
            for (int c = 0; c < 4; c++) {
                int j = 4*tj + c;
                if (i < NI && j < i)
                    prow[EMBD + i*(i-1)/2 + j] = acc[a][c];
            }
        }
    }
}

// ---------------------------------------------------------------------------
// Final layer: out[b] = dot(relu(t2[b]), tw2) + tb2   (N=1)
// ---------------------------------------------------------------------------
__global__ __launch_bounds__(128)
void final_kernel(const float* __restrict__ w,
                  const float* __restrict__ bias,
                  float* __restrict__ out)
{
    const int warp = blockIdx.x * 4 + (threadIdx.x >> 5);
    const int lane = threadIdx.x & 31;
    if (warp >= BATCH) return;

    const float* row = g_scratch + OFF_T2 + (size_t)warp * 256;
    float s = 0.f;
    #pragma unroll
    for (int d = lane; d < 256; d += 32) {
        float v = fmaxf(row[d], 0.f);
        s += v * w[d];
    }
    #pragma unroll
    for (int o = 16; o; o >>= 1) s += __shfl_xor_sync(0xffffffffu, s, o);
    if (lane == 0) out[warp] = s + bias[0];
}

// ---------------------------------------------------------------------------
// Launch sequence
// ---------------------------------------------------------------------------
extern "C" void kernel_launch(void* const* d_in, const int* in_sizes, int n_in,
                              void* d_out, int out_size)
{
    const float* dense_x = (const float*)d_in[0];
    const int*   sidx    = (const int*)d_in[1];
    const float* emb     = (const float*)d_in[2];
    const float* bw0 = (const float*)d_in[3];
    const float* bb0 = (const float*)d_in[4];
    const float* bw1 = (const float*)d_in[5];
    const float* bb1 = (const float*)d_in[6];
    const float* bw2 = (const float*)d_in[7];
    const float* bb2 = (const float*)d_in[8];
    const float* tw0 = (const float*)d_in[9];
    const float* tb0 = (const float*)d_in[10];
    const float* tw1 = (const float*)d_in[11];
    const float* tb1 = (const float*)d_in[12];
    const float* tw2 = (const float*)d_in[13];
    const float* tb2 = (const float*)d_in[14];
    float* out = (float*)d_out;

    // Bottom MLP
    {
        dim3 grid(512/64, BATCH/128);
        gemm_kernel<128,64,16,8,4,false><<<grid, 256>>>(dense_x, 0, bw0, bb0,
                                                        OFF_H1, BATCH, 512, MDEN);
    }
    {
        dim3 grid(256/64, BATCH/128);
        gemm_kernel<128,64,16,8,4,true><<<grid, 256>>>(nullptr, OFF_H1, bw1, bb1,
                                                       OFF_H2, BATCH, 256, 512);
    }
    {
        dim3 grid(64/64, BATCH/64);
        gemm_kernel<64,64,16,4,4,true><<<grid, 256>>>(nullptr, OFF_H2, bw2, bb2,
                                                      OFF_XB, BATCH, 64, 256);
    }

    // Embedding gather + pairwise interaction -> P [4096,415]
    interact_kernel<<<BATCH/4, 128>>>(sidx, emb);

    // Top MLP
    {
        dim3 grid(512/64, BATCH/128);
        gemm_kernel<128,64,16,8,4,false><<<grid, 256>>>(nullptr, OFF_P, tw0, tb0,
                                                        OFF_T1, BATCH, 512, TOPIN);
    }
    {
        dim3 grid(256/64, BATCH/128);
        gemm_kernel<128,64,16,8,4,true><<<grid, 256>>>(nullptr, OFF_T1, tw1, tb1,
                                                       OFF_T2, BATCH, 256, 512);
    }
    final_kernel<<<BATCH/4, 128>>>(tw2, tb2, out);
}

// round 4
// speedup vs baseline: 2.2881x; 1.8451x over previous
#include <cuda_runtime.h>
#include <math.h>

// ---------------------------------------------------------------------------
// DLRM forward: bottom MLP -> embedding gather + pairwise interaction -> top MLP
// B=4096, M_DEN=13, N_EMB=26, EMB_DIM=64, NI=27, N_PAIRS=351
// LN_BOT: 13 -> 512 -> 256 -> 64 ; LN_TOP: 415 -> 512 -> 256 -> 1
// All GEMM K dims padded to multiples of 16 (zero-padded weights => exact).
// ---------------------------------------------------------------------------

#define BATCH   4096
#define MDEN    13
#define NEMB    26
#define NI      27
#define NPAIRS  351
#define EMBD    64
#define VOCAB   100000
#define TOPIN   415
#define TOPINP  416     // padded

// Scratch layout (floats)
#define OFF_H1   0                                // [4096,512]
#define OFF_H2   (OFF_H1  + BATCH*512)            // [4096,256]
#define OFF_P    (OFF_H2  + BATCH*256)            // [4096,416] (cols 0:64 = x_bot)
#define OFF_T1   (OFF_P   + BATCH*TOPINP)         // [4096,512]
#define OFF_T2   (OFF_T1  + BATCH*512)            // [4096,256]
#define OFF_XPAD (OFF_T2  + BATCH*256)            // [4096,16]  dense_x padded
#define OFF_PW0  (OFF_XPAD+ BATCH*16)             // [512,16]   bw0 padded
#define OFF_PTW0 (OFF_PW0 + 512*16)               // [512,416]  tw0 padded
#define SCRATCH_TOTAL (OFF_PTW0 + 512*TOPINP)

__device__ __align__(16) float g_scratch[SCRATCH_TOTAL];

// ---------------------------------------------------------------------------
// Prep: pad dense_x, bw0, tw0 into scratch (zero pad columns).
// ---------------------------------------------------------------------------
__global__ void prep_kernel(const float* __restrict__ dense_x,
                            const float* __restrict__ bw0,
                            const float* __restrict__ tw0)
{
    int tid = blockIdx.x * blockDim.x + threadIdx.x;
    int stride = gridDim.x * blockDim.x;

    // XPAD [4096,16]
    for (int i = tid; i < BATCH * 16; i += stride) {
        int r = i >> 4, c = i & 15;
        g_scratch[OFF_XPAD + i] = (c < MDEN) ? dense_x[r * MDEN + c] : 0.f;
    }
    // PW0 [512,16]
    for (int i = tid; i < 512 * 16; i += stride) {
        int r = i >> 4, c = i & 15;
        g_scratch[OFF_PW0 + i] = (c < MDEN) ? bw0[r * MDEN + c] : 0.f;
    }
    // PTW0 [512,416]
    for (int i = tid; i < 512 * TOPINP; i += stride) {
        int r = i / TOPINP, c = i % TOPINP;
        g_scratch[OFF_PTW0 + i] = (c < TOPIN) ? tw0[r * TOPIN + c] : 0.f;
    }
}

// ---------------------------------------------------------------------------
// Tiled SGEMM: C[M,N] = act(A)[M,K] @ W[N,K]^T + bias[N]
// K compile-time, multiple of 16. float4 global loads, register-prefetch
// double buffering. A/W optionally from scratch via offsets.
// ---------------------------------------------------------------------------
template<int K, int BM, int BN, int BK, int TM, int TN, bool RELU>
__global__ __launch_bounds__((BM/TM)*(BN/TN))
void gemm_kernel(const float* __restrict__ Aext, int aoff,
                 const float* __restrict__ Wext, int woff,
                 const float* __restrict__ bias,
                 int coff, int cstride, int N)
{
    constexpr int THREADS = (BM/TM)*(BN/TN);
    constexpr int KQ  = BK / 4;
    constexpr int AF4 = BM*BK/(4*THREADS);
    constexpr int WF4 = BN*BK/(4*THREADS);
    static_assert(AF4 >= 1 && WF4 >= 1, "tile/thread mismatch");

    __shared__ float As[BK][BM + 4];
    __shared__ float Ws[BK][BN + 4];

    const float* A = Aext ? Aext : (const float*)g_scratch + aoff;
    const float* W = Wext ? Wext : (const float*)g_scratch + woff;
    float* C = g_scratch + coff;

    const int tid = threadIdx.x;
    const int tx  = tid % (BN/TN);
    const int ty  = tid / (BN/TN);
    const int m0  = blockIdx.y * BM;
    const int n0  = blockIdx.x * BN;

    float4 pa[AF4], pw[WF4];

    // prefetch tile 0
    #pragma unroll
    for (int i = 0; i < AF4; i++) {
        int f = tid + i*THREADS, r = f / KQ, kq = f % KQ;
        pa[i] = *(const float4*)&A[(size_t)(m0 + r) * K + kq*4];
    }
    #pragma unroll
    for (int i = 0; i < WF4; i++) {
        int f = tid + i*THREADS, r = f / KQ, kq = f % KQ;
        pw[i] = *(const float4*)&W[(size_t)(n0 + r) * K + kq*4];
    }

    float acc[TM][TN];
    #pragma unroll
    for (int i = 0; i < TM; i++)
        #pragma unroll
        for (int j = 0; j < TN; j++)
            acc[i][j] = 0.f;

    for (int k0 = 0; k0 < K; k0 += BK) {
        // commit prefetched tile to smem (transposed), ReLU fused on A
        #pragma unroll
        for (int i = 0; i < AF4; i++) {
            int f = tid + i*THREADS, r = f / KQ, kq = f % KQ;
            float4 v = pa[i];
            if (RELU) { v.x=fmaxf(v.x,0.f); v.y=fmaxf(v.y,0.f);
                        v.z=fmaxf(v.z,0.f); v.w=fmaxf(v.w,0.f); }
            As[kq*4+0][r] = v.x; As[kq*4+1][r] = v.y;
            As[kq*4+2][r] = v.z; As[kq*4+3][r] = v.w;
        }
        #pragma unroll
        for (int i = 0; i < WF4; i++) {
            int f = tid + i*THREADS, r = f / KQ, kq = f % KQ;
            float4 v = pw[i];
            Ws[kq*4+0][r] = v.x; Ws[kq*4+1][r] = v.y;
            Ws[kq*4+2][r] = v.z; Ws[kq*4+3][r] = v.w;
        }
        __syncthreads();

        // prefetch next tile while computing this one
        if (k0 + BK < K) {
            #pragma unroll
            for (int i = 0; i < AF4; i++) {
                int f = tid + i*THREADS, r = f / KQ, kq = f % KQ;
                pa[i] = *(const float4*)&A[(size_t)(m0 + r) * K + k0 + BK + kq*4];
            }
            #pragma unroll
            for (int i = 0; i < WF4; i++) {
                int f = tid + i*THREADS, r = f / KQ, kq = f % KQ;
                pw[i] = *(const float4*)&W[(size_t)(n0 + r) * K + k0 + BK + kq*4];
            }
        }

        #pragma unroll
        for (int k = 0; k < BK; k++) {
            float ra[TM], rw[TN];
            #pragma unroll
            for (int i = 0; i < TM; i += 4) {
                float4 t = *(const float4*)&As[k][ty*TM + i];
                ra[i]=t.x; ra[i+1]=t.y; ra[i+2]=t.z; ra[i+3]=t.w;
            }
            #pragma unroll
            for (int j = 0; j < TN; j += 4) {
                float4 t = *(const float4*)&Ws[k][tx*TN + j];
                rw[j]=t.x; rw[j+1]=t.y; rw[j+2]=t.z; rw[j+3]=t.w;
            }
            #pragma unroll
            for (int i = 0; i < TM; i++)
                #pragma unroll
                for (int j = 0; j < TN; j++)
                    acc[i][j] += ra[i] * rw[j];
        }
        __syncthreads();
    }

    // Epilogue: bias + float4 stores
    #pragma unroll
    for (int i = 0; i < TM; i++) {
        int m = m0 + ty*TM + i;
        #pragma unroll
        for (int j = 0; j < TN; j += 4) {
            int n = n0 + tx*TN + j;
            float4 r;
            r.x = acc[i][j+0] + bias[n+0];
            r.y = acc[i][j+1] + bias[n+1];
            r.z = acc[i][j+2] + bias[n+2];
            r.w = acc[i][j+3] + bias[n+3];
            *(float4*)&C[(size_t)m * cstride + n] = r;
        }
    }
}

// ---------------------------------------------------------------------------
// Interaction kernel. One warp per batch row, 4 warps/block.
// x_bot already sits in P[b][0:64] (written by bot-L2 GEMM with stride 416).
// Gather fully unrolled in 3 phases for high MLP.
// ---------------------------------------------------------------------------
#define IPAD 28

__global__ __launch_bounds__(128)
void interact_kernel(const int* __restrict__ sidx,
                     const float* __restrict__ emb)
{
    __shared__ __align__(16) float Tt[4][EMBD][IPAD];

    const int w    = threadIdx.x >> 5;
    const int lane = threadIdx.x & 31;
    const int b    = blockIdx.x * 4 + w;

    float* prow = g_scratch + OFF_P + (size_t)b * TOPINP;
    float (*T)[IPAD] = Tt[w];

    // Phase 1: all source pointers
    const float* srcs[NI];
    srcs[0] = prow;                      // x_bot in place
    #pragma unroll
    for (int r = 1; r < NI; r++) {
        int ix = sidx[(size_t)(r - 1) * BATCH + b];
        ix = ix < 0 ? 0 : (ix >= VOCAB ? VOCAB - 1 : ix);
        srcs[r] = emb + ((size_t)(r - 1) * VOCAB + (size_t)ix) * EMBD;
    }
    // Phase 2: issue all loads (MLP ~27)
    float2 vbuf[NI];
    #pragma unroll
    for (int r = 0; r < NI; r++)
        vbuf[r] = ((const float2*)srcs[r])[lane];
    // Phase 3: scatter transposed into SMEM
    #pragma unroll
    for (int r = 0; r < NI; r++) {
        T[2*lane    ][r] = vbuf[r].x;
        T[2*lane + 1][r] = vbuf[r].y;
    }
    __syncwarp();

    if (lane == 0) prow[TOPINP - 1] = 0.f;   // pad column (harmless; W pad is 0)

    if (lane < 28) {
        // lane -> lower-triangle 4x4 tile (ti, tj), ti in 0..6, tj <= ti
        int ti = 0;
        while ((ti + 1) * (ti + 2) / 2 <= lane) ti++;
        int tj = lane - ti * (ti + 1) / 2;

        float acc[4][4];
        #pragma unroll
        for (int a = 0; a < 4; a++)
            #pragma unroll
            for (int c = 0; c < 4; c++)
                acc[a][c] = 0.f;

        #pragma unroll 8
        for (int k = 0; k < EMBD; k++) {
            float4 av = *(const float4*)&T[k][4*ti];
            float4 bv = *(const float4*)&T[k][4*tj];
            float ra[4] = {av.x, av.y, av.z, av.w};
            float rb[4] = {bv.x, bv.y, bv.z, bv.w};
            #pragma unroll
            for (int a = 0; a < 4; a++)
                #pragma unroll
                for (int c = 0; c < 4; c++)
                    acc[a][c] += ra[a] * rb[c];
        }

        #pragma unroll
        for (int a = 0; a < 4; a++) {
            int i = 4*ti + a;
            #pragma unroll
            for (int c = 0; c < 4; c++) {
                int j = 4*tj + c;
                if (i < NI && j < i)
                    prow[EMBD + i*(i-1)/2 + j] = acc[a][c];
            }
        }
    }
}

// ---------------------------------------------------------------------------
// Final layer: out[b] = dot(relu(t2[b]), tw2) + tb2
// ---------------------------------------------------------------------------
__global__ __launch_bounds__(128)
void final_kernel(const float* __restrict__ w,
                  const float* __restrict__ bias,
                  float* __restrict__ out)
{
    const int warp = blockIdx.x * 4 + (threadIdx.x >> 5);
    const int lane = threadIdx.x & 31;
    if (warp >= BATCH) return;

    const float* row = g_scratch + OFF_T2 + (size_t)warp * 256;
    float s = 0.f;
    #pragma unroll
    for (int d = lane; d < 256; d += 32) {
        float v = fmaxf(row[d], 0.f);
        s += v * w[d];
    }
    #pragma unroll
    for (int o = 16; o; o >>= 1) s += __shfl_xor_sync(0xffffffffu, s, o);
    if (lane == 0) out[warp] = s + bias[0];
}

// ---------------------------------------------------------------------------
// Launch sequence
// ---------------------------------------------------------------------------
extern "C" void kernel_launch(void* const* d_in, const int* in_sizes, int n_in,
                              void* d_out, int out_size)
{
    const float* dense_x = (const float*)d_in[0];
    const int*   sidx    = (const int*)d_in[1];
    const float* emb     = (const float*)d_in[2];
    const float* bb0 = (const float*)d_in[4];
    const float* bw1 = (const float*)d_in[5];
    const float* bb1 = (const float*)d_in[6];
    const float* bw2 = (const float*)d_in[7];
    const float* bb2 = (const float*)d_in[8];
    const float* tb0 = (const float*)d_in[10];
    const float* tw1 = (const float*)d_in[11];
    const float* tb1 = (const float*)d_in[12];
    const float* tw2 = (const float*)d_in[13];
    const float* tb2 = (const float*)d_in[14];
    const float* bw0 = (const float*)d_in[3];
    const float* tw0 = (const float*)d_in[9];
    float* out = (float*)d_out;

    // Pad dense_x / bw0 / tw0 into scratch
    prep_kernel<<<256, 256>>>(dense_x, bw0, tw0);

    // Bottom MLP
    {   // L0: XPAD[4096,16] @ PW0[512,16]^T -> H1
        dim3 grid(512/64, BATCH/128);
        gemm_kernel<16,128,64,16,8,4,false><<<grid, 256>>>(
            nullptr, OFF_XPAD, nullptr, OFF_PW0, bb0, OFF_H1, 512, 512);
    }
    {   // L1: relu(H1)[4096,512] @ bw1[256,512]^T -> H2
        dim3 grid(256/64, BATCH/128);
        gemm_kernel<512,128,64,16,8,4,true><<<grid, 256>>>(
            nullptr, OFF_H1, bw1, 0, bb1, OFF_H2, 256, 256);
    }
    {   // L2: relu(H2)[4096,256] @ bw2[64,256]^T -> P[:,0:64] (stride 416)
        dim3 grid(64/64, BATCH/32);
        gemm_kernel<256,32,64,16,4,4,true><<<grid, 128>>>(
            nullptr, OFF_H2, bw2, 0, bb2, OFF_P, TOPINP, 64);
    }

    // Embedding gather + pairwise interaction -> P[:,64:415]
    interact_kernel<<<BATCH/4, 128>>>(sidx, emb);

    // Top MLP
    {   // L0: P[4096,416] @ PTW0[512,416]^T -> T1
        dim3 grid(512/64, BATCH/128);
        gemm_kernel<TOPINP,128,64,16,8,4,false><<<grid, 256>>>(
            nullptr, OFF_P, nullptr, OFF_PTW0, tb0, OFF_T1, 512, 512);
    }
    {   // L1: relu(T1)[4096,512] @ tw1[256,512]^T -> T2
        dim3 grid(256/64, BATCH/128);
        gemm_kernel<512,128,64,16,8,4,true><<<grid, 256>>>(
            nullptr, OFF_T1, tw1, 0, tb1, OFF_T2, 256, 256);
    }
    final_kernel<<<BATCH/4, 128>>>(tw2, tb2, out);
}

// round 6
// speedup vs baseline: 2.5354x; 1.1081x over previous
#include <cuda_runtime.h>
#include <cstdint>
#include <math.h>

// ---------------------------------------------------------------------------
// DLRM forward. GEMMs via mma.sync tf32 (legacy tensor path, sm_103-safe).
// B=4096; bot: 13(->32)->512->256->64 ; top: 415(->512)->512->256->1
// ---------------------------------------------------------------------------

#define BATCH   4096
#define MDEN    13
#define NI      27
#define EMBD    64
#define VOCAB   100000
#define TOPIN   415
#define PDIM    512      // padded P width (K of top-L0)
#define XK      32       // padded dense K

// Scratch layout (floats)
#define OFF_H1   0                                 // [4096,512]
#define OFF_H2   (OFF_H1  + BATCH*512)             // [4096,256]
#define OFF_P    (OFF_H2  + BATCH*256)             // [4096,512]
#define OFF_T1   (OFF_P   + BATCH*PDIM)            // [4096,512]
#define OFF_T2   (OFF_T1  + BATCH*512)             // [4096,256]
#define OFF_XPAD (OFF_T2  + BATCH*256)             // [4096,32]
#define OFF_PW0  (OFF_XPAD+ BATCH*XK)              // [512,32]
#define OFF_PTW0 (OFF_PW0 + 512*XK)                // [512,512]
#define SCRATCH_TOTAL (OFF_PTW0 + 512*PDIM)

__device__ __align__(16) float g_scratch[SCRATCH_TOTAL];

__device__ __forceinline__ uint32_t f2tf32(float x) {
    uint32_t u;
    asm("cvt.rna.tf32.f32 %0, %1;" : "=r"(u) : "f"(x));
    return u;
}

__device__ __forceinline__ void mma_tf32(float* c,
                                         uint32_t a0, uint32_t a1, uint32_t a2, uint32_t a3,
                                         uint32_t b0, uint32_t b1) {
    asm volatile(
        "mma.sync.aligned.m16n8k8.row.col.f32.tf32.tf32.f32 "
        "{%0,%1,%2,%3}, {%4,%5,%6,%7}, {%8,%9}, {%0,%1,%2,%3};"
        : "+f"(c[0]), "+f"(c[1]), "+f"(c[2]), "+f"(c[3])
        : "r"(a0), "r"(a1), "r"(a2), "r"(a3), "r"(b0), "r"(b1));
}

// ---------------------------------------------------------------------------
// Prep: pad dense_x->XPAD[4096,32], bw0->PW0[512,32], tw0->PTW0[512,512],
// zero P pad columns [415..512).
// ---------------------------------------------------------------------------
__global__ void prep_kernel(const float* __restrict__ dense_x,
                            const float* __restrict__ bw0,
                            const float* __restrict__ tw0)
{
    int tid = blockIdx.x * blockDim.x + threadIdx.x;
    int stride = gridDim.x * blockDim.x;

    for (int i = tid; i < BATCH * XK; i += stride) {
        int r = i / XK, c = i % XK;
        g_scratch[OFF_XPAD + i] = (c < MDEN) ? dense_x[r * MDEN + c] : 0.f;
    }
    for (int i = tid; i < 512 * XK; i += stride) {
        int r = i / XK, c = i % XK;
        g_scratch[OFF_PW0 + i] = (c < MDEN) ? bw0[r * MDEN + c] : 0.f;
    }
    for (int i = tid; i < 512 * PDIM; i += stride) {
        int r = i / PDIM, c = i % PDIM;
        g_scratch[OFF_PTW0 + i] = (c < TOPIN) ? tw0[r * TOPIN + c] : 0.f;
    }
    for (int i = tid; i < BATCH * (PDIM - TOPIN); i += stride) {
        int r = i / (PDIM - TOPIN), c = TOPIN + i % (PDIM - TOPIN);
        g_scratch[OFF_P + (size_t)r * PDIM + c] = 0.f;
    }
}

// ---------------------------------------------------------------------------
// Tensor-core GEMM via mma.sync tf32:
//   C[M, N] = act(A)[M,K] @ W[N,K]^T + bias[N]
// CTA tile BM x BN, BK=32. Warp tile 32x32 (2 x m16 tiles, 4 x n8 tiles).
// A/W staged in smem as tf32 words, +8 pad => conflict-free fragment loads.
// Register-prefetch double buffering on the global loads. ReLU fused on A.
// ---------------------------------------------------------------------------
template<int K, int BM, int BN, bool RELU>
__global__ __launch_bounds__((BM/32)*(BN/32)*32)
void mma_gemm(const float* __restrict__ Aext, int aoff,
              const float* __restrict__ Wext, int woff,
              const float* __restrict__ bias,
              int coff, int cstride)
{
    constexpr int WARPS_N = BN / 32;
    constexpr int THREADS = (BM/32) * WARPS_N * 32;
    constexpr int BK  = 32;
    constexpr int KQ  = BK / 4;                 // float4s per row-chunk
    constexpr int AF4 = BM * KQ / THREADS;
    constexpr int WF4 = BN * KQ / THREADS;
    static_assert(AF4 >= 1 && WF4 >= 1, "tile config");

    __shared__ uint32_t As[BK][BM + 8];
    __shared__ uint32_t Ws[BK][BN + 8];

    const float* A = Aext ? Aext : (const float*)g_scratch + aoff;
    const float* W = Wext ? Wext : (const float*)g_scratch + woff;
    float* C = g_scratch + coff;

    const int tid  = threadIdx.x;
    const int wid  = tid >> 5;
    const int lane = tid & 31;
    const int qr   = lane & 3;     // threadID_in_group
    const int gr   = lane >> 2;    // groupID
    const int wn0  = (wid % WARPS_N) * 32;
    const int wm0  = (wid / WARPS_N) * 32;
    const int m0   = blockIdx.y * BM;
    const int n0   = blockIdx.x * BN;

    float4 pa[AF4], pw[WF4];
    #pragma unroll
    for (int i = 0; i < AF4; i++) {
        int f = tid + i*THREADS, r = f / KQ, kq = f % KQ;
        pa[i] = *(const float4*)&A[(size_t)(m0 + r) * K + kq*4];
    }
    #pragma unroll
    for (int i = 0; i < WF4; i++) {
        int f = tid + i*THREADS, r = f / KQ, kq = f % KQ;
        pw[i] = *(const float4*)&W[(size_t)(n0 + r) * K + kq*4];
    }

    float acc[2][4][4];
    #pragma unroll
    for (int mt = 0; mt < 2; mt++)
        #pragma unroll
        for (int nt = 0; nt < 4; nt++)
            #pragma unroll
            for (int e = 0; e < 4; e++)
                acc[mt][nt][e] = 0.f;

    for (int k0 = 0; k0 < K; k0 += BK) {
        // commit prefetched tiles (convert to tf32)
        #pragma unroll
        for (int i = 0; i < AF4; i++) {
            int f = tid + i*THREADS, r = f / KQ, kq = f % KQ;
            float4 v = pa[i];
            if (RELU) { v.x=fmaxf(v.x,0.f); v.y=fmaxf(v.y,0.f);
                        v.z=fmaxf(v.z,0.f); v.w=fmaxf(v.w,0.f); }
            As[kq*4+0][r] = f2tf32(v.x);
            As[kq*4+1][r] = f2tf32(v.y);
            As[kq*4+2][r] = f2tf32(v.z);
            As[kq*4+3][r] = f2tf32(v.w);
        }
        #pragma unroll
        for (int i = 0; i < WF4; i++) {
            int f = tid + i*THREADS, r = f / KQ, kq = f % KQ;
            float4 v = pw[i];
            Ws[kq*4+0][r] = f2tf32(v.x);
            Ws[kq*4+1][r] = f2tf32(v.y);
            Ws[kq*4+2][r] = f2tf32(v.z);
            Ws[kq*4+3][r] = f2tf32(v.w);
        }
        __syncthreads();

        // prefetch next tile
        if (k0 + BK < K) {
            #pragma unroll
            for (int i = 0; i < AF4; i++) {
                int f = tid + i*THREADS, r = f / KQ, kq = f % KQ;
                pa[i] = *(const float4*)&A[(size_t)(m0 + r) * K + k0 + BK + kq*4];
            }
            #pragma unroll
            for (int i = 0; i < WF4; i++) {
                int f = tid + i*THREADS, r = f / KQ, kq = f % KQ;
                pw[i] = *(const float4*)&W[(size_t)(n0 + r) * K + k0 + BK + kq*4];
            }
        }

        // 4 k-steps of m16n8k8
        #pragma unroll
        for (int kk = 0; kk < BK; kk += 8) {
            uint32_t af[2][4];
            #pragma unroll
            for (int mt = 0; mt < 2; mt++) {
                int m = wm0 + mt*16 + gr;
                af[mt][0] = As[kk + qr    ][m];
                af[mt][1] = As[kk + qr    ][m + 8];
                af[mt][2] = As[kk + qr + 4][m];
                af[mt][3] = As[kk + qr + 4][m + 8];
            }
            uint32_t bf[4][2];
            #pragma unroll
            for (int nt = 0; nt < 4; nt++) {
                int n = wn0 + nt*8 + gr;
                bf[nt][0] = Ws[kk + qr    ][n];
                bf[nt][1] = Ws[kk + qr + 4][n];
            }
            #pragma unroll
            for (int mt = 0; mt < 2; mt++)
                #pragma unroll
                for (int nt = 0; nt < 4; nt++)
                    mma_tf32(acc[mt][nt], af[mt][0], af[mt][1], af[mt][2], af[mt][3],
                             bf[nt][0], bf[nt][1]);
        }
        __syncthreads();
    }

    // epilogue: bias + store (float2 per c-pair)
    #pragma unroll
    for (int mt = 0; mt < 2; mt++) {
        int row = m0 + wm0 + mt*16 + gr;
        #pragma unroll
        for (int nt = 0; nt < 4; nt++) {
            int col = n0 + wn0 + nt*8 + 2*qr;
            float bx = bias[col], by = bias[col + 1];
            float2 v0 = { acc[mt][nt][0] + bx, acc[mt][nt][1] + by };
            float2 v1 = { acc[mt][nt][2] + bx, acc[mt][nt][3] + by };
            *(float2*)&C[(size_t)row * cstride + col] = v0;
            *(float2*)&C[(size_t)(row + 8) * cstride + col] = v1;
        }
    }
}

// ---------------------------------------------------------------------------
// Interaction kernel. One warp per batch row; x_bot already in P[b][0:64].
// ---------------------------------------------------------------------------
#define IPAD 28

__global__ __launch_bounds__(128)
void interact_kernel(const int* __restrict__ sidx,
                     const float* __restrict__ emb)
{
    __shared__ __align__(16) float Tt[4][EMBD][IPAD];

    const int w    = threadIdx.x >> 5;
    const int lane = threadIdx.x & 31;
    const int b    = blockIdx.x * 4 + w;

    float* prow = g_scratch + OFF_P + (size_t)b * PDIM;
    float (*T)[IPAD] = Tt[w];

    const float* srcs[NI];
    srcs[0] = prow;
    #pragma unroll
    for (int r = 1; r < NI; r++) {
        int ix = sidx[(size_t)(r - 1) * BATCH + b];
        ix = ix < 0 ? 0 : (ix >= VOCAB ? VOCAB - 1 : ix);
        srcs[r] = emb + ((size_t)(r - 1) * VOCAB + (size_t)ix) * EMBD;
    }
    float2 vbuf[NI];
    #pragma unroll
    for (int r = 0; r < NI; r++)
        vbuf[r] = ((const float2*)srcs[r])[lane];
    #pragma unroll
    for (int r = 0; r < NI; r++) {
        T[2*lane    ][r] = vbuf[r].x;
        T[2*lane + 1][r] = vbuf[r].y;
    }
    __syncwarp();

    if (lane < 28) {
        int ti = 0;
        while ((ti + 1) * (ti + 2) / 2 <= lane) ti++;
        int tj = lane - ti * (ti + 1) / 2;

        float acc[4][4];
        #pragma unroll
        for (int a = 0; a < 4; a++)
            #pragma unroll
            for (int c = 0; c < 4; c++)
                acc[a][c] = 0.f;

        #pragma unroll 8
        for (int k = 0; k < EMBD; k++) {
            float4 av = *(const float4*)&T[k][4*ti];
            float4 bv = *(const float4*)&T[k][4*tj];
            float ra[4] = {av.x, av.y, av.z, av.w};
            float rb[4] = {bv.x, bv.y, bv.z, bv.w};
            #pragma unroll
            for (int a = 0; a < 4; a++)
                #pragma unroll
                for (int c = 0; c < 4; c++)
                    acc[a][c] += ra[a] * rb[c];
        }

        #pragma unroll
        for (int a = 0; a < 4; a++) {
            int i = 4*ti + a;
            #pragma unroll
            for (int c = 0; c < 4; c++) {
                int j = 4*tj + c;
                if (i < NI && j < i)
                    prow[EMBD + i*(i-1)/2 + j] = acc[a][c];
            }
        }
    }
}

// ---------------------------------------------------------------------------
// Final layer: out[b] = dot(relu(t2[b]), tw2) + tb2
// ---------------------------------------------------------------------------
__global__ __launch_bounds__(128)
void final_kernel(const float* __restrict__ w,
                  const float* __restrict__ bias,
                  float* __restrict__ out)
{
    const int warp = blockIdx.x * 4 + (threadIdx.x >> 5);
    const int lane = threadIdx.x & 31;
    if (warp >= BATCH) return;

    const float* row = g_scratch + OFF_T2 + (size_t)warp * 256;
    float s = 0.f;
    #pragma unroll
    for (int d = lane; d < 256; d += 32) {
        float v = fmaxf(row[d], 0.f);
        s += v * w[d];
    }
    #pragma unroll
    for (int o = 16; o; o >>= 1) s += __shfl_xor_sync(0xffffffffu, s, o);
    if (lane == 0) out[warp] = s + bias[0];
}

// ---------------------------------------------------------------------------
// Launch sequence
// ---------------------------------------------------------------------------
extern "C" void kernel_launch(void* const* d_in, const int* in_sizes, int n_in,
                              void* d_out, int out_size)
{
    const float* dense_x = (const float*)d_in[0];
    const int*   sidx    = (const int*)d_in[1];
    const float* emb     = (const float*)d_in[2];
    const float* bw0 = (const float*)d_in[3];
    const float* bb0 = (const float*)d_in[4];
    const float* bw1 = (const float*)d_in[5];
    const float* bb1 = (const float*)d_in[6];
    const float* bw2 = (const float*)d_in[7];
    const float* bb2 = (const float*)d_in[8];
    const float* tw0 = (const float*)d_in[9];
    const float* tb0 = (const float*)d_in[10];
    const float* tw1 = (const float*)d_in[11];
    const float* tb1 = (const float*)d_in[12];
    const float* tw2 = (const float*)d_in[13];
    const float* tb2 = (const float*)d_in[14];
    float* out = (float*)d_out;

    // Pad inputs / weights, zero P pad columns
    prep_kernel<<<256, 256>>>(dense_x, bw0, tw0);

    // bot-L0: XPAD[4096,32] @ PW0[512,32]^T -> H1
    {
        dim3 grid(512/64, BATCH/128);
        mma_gemm<XK,128,64,false><<<grid, 256>>>(
            nullptr, OFF_XPAD, nullptr, OFF_PW0, bb0, OFF_H1, 512);
    }
    // bot-L1: relu(H1)[4096,512] @ bw1[256,512]^T -> H2
    {
        dim3 grid(256/64, BATCH/128);
        mma_gemm<512,128,64,true><<<grid, 256>>>(
            nullptr, OFF_H1, bw1, 0, bb1, OFF_H2, 256);
    }
    // bot-L2: relu(H2)[4096,256] @ bw2[64,256]^T -> P[:,0:64] (stride 512)
    {
        dim3 grid(1, BATCH/64);
        mma_gemm<256,64,64,true><<<grid, 128>>>(
            nullptr, OFF_H2, bw2, 0, bb2, OFF_P, PDIM);
    }

    // gather + interaction -> P[:,64:415]
    interact_kernel<<<BATCH/4, 128>>>(sidx, emb);

    // top-L0: P[4096,512] @ PTW0[512,512]^T -> T1
    {
        dim3 grid(512/64, BATCH/128);
        mma_gemm<512,128,64,false><<<grid, 256>>>(
            nullptr, OFF_P, nullptr, OFF_PTW0, tb0, OFF_T1, 512);
    }
    // top-L1: relu(T1)[4096,512] @ tw1[256,512]^T -> T2
    {
        dim3 grid(256/64, BATCH/128);
        mma_gemm<512,128,64,true><<<grid, 256>>>(
            nullptr, OFF_T1, tw1, 0, tb1, OFF_T2, 256);
    }
    final_kernel<<<BATCH/4, 128>>>(tw2, tb2, out);
}

// round 7
// speedup vs baseline: 4.7097x; 1.8576x over previous
#include <cuda_runtime.h>
#include <cuda_fp16.h>
#include <cstdint>
#include <math.h>

// ---------------------------------------------------------------------------
// DLRM forward. GEMMs via mma.sync m16n8k16 fp16 (fp32 accum), sm_103-safe.
// B=4096; bot: 13(->32)->512->256->64 ; top: 415(->512)->512->256->1
// Weights pre-converted to fp16 once. Final layer fused into top-L1 epilogue.
// ---------------------------------------------------------------------------

#define BATCH   4096
#define MDEN    13
#define NI      27
#define EMBD    64
#define VOCAB   100000
#define TOPIN   415
#define PDIM    512
#define XK      32

// fp32 scratch
#define OFF_H1   0                                 // [4096,512]
#define OFF_H2   (OFF_H1  + BATCH*512)             // [4096,256]
#define OFF_P    (OFF_H2  + BATCH*256)             // [4096,512]
#define OFF_T1   (OFF_P   + BATCH*PDIM)            // [4096,512]
#define OFF_XPAD (OFF_T1  + BATCH*512)             // [4096,32]
#define SCRATCH_TOTAL (OFF_XPAD + BATCH*XK)
__device__ __align__(16) float g_scratch[SCRATCH_TOTAL];

// fp16 weights
#define HW0   0                     // [512,32]
#define HW1   (HW0  + 512*XK)       // [256,512]
#define HW2   (HW1  + 256*512)      // [64,256]
#define HTW0  (HW2  + 64*256)       // [512,512]
#define HTW1  (HTW0 + 512*512)      // [256,512]
#define HTOTAL (HTW1 + 256*512)
__device__ __align__(16) __half g_wh[HTOTAL];

__device__ __forceinline__ uint32_t smem_u32(const void* p) {
    uint32_t a;
    asm("{ .reg .u64 t; cvta.to.shared.u64 t, %1; cvt.u32.u64 %0, t; }"
        : "=r"(a) : "l"(p));
    return a;
}

__device__ __forceinline__ void mma_f16(float* c, uint32_t a0, uint32_t a1,
                                        uint32_t a2, uint32_t a3,
                                        uint32_t b0, uint32_t b1) {
    asm volatile(
        "mma.sync.aligned.m16n8k16.row.col.f32.f16.f16.f32 "
        "{%0,%1,%2,%3}, {%4,%5,%6,%7}, {%8,%9}, {%0,%1,%2,%3};"
        : "+f"(c[0]), "+f"(c[1]), "+f"(c[2]), "+f"(c[3])
        : "r"(a0), "r"(a1), "r"(a2), "r"(a3), "r"(b0), "r"(b1));
}

__device__ __forceinline__ void ldm_x4(uint32_t* r, uint32_t addr) {
    asm volatile("ldmatrix.sync.aligned.m8n8.x4.shared.b16 {%0,%1,%2,%3}, [%4];"
                 : "=r"(r[0]), "=r"(r[1]), "=r"(r[2]), "=r"(r[3]) : "r"(addr));
}

// ---------------------------------------------------------------------------
// Prep: pad dense_x -> XPAD; convert/pad all GEMM weights to fp16;
// zero P pad cols; init out[b] = tb2[0].
// ---------------------------------------------------------------------------
__global__ void prep_kernel(const float* __restrict__ dense_x,
                            const float* __restrict__ bw0,
                            const float* __restrict__ bw1,
                            const float* __restrict__ bw2,
                            const float* __restrict__ tw0,
                            const float* __restrict__ tw1,
                            const float* __restrict__ tb2,
                            float* __restrict__ out)
{
    int tid = blockIdx.x * blockDim.x + threadIdx.x;
    int stride = gridDim.x * blockDim.x;

    for (int i = tid; i < BATCH * XK; i += stride) {
        int r = i / XK, c = i % XK;
        g_scratch[OFF_XPAD + i] = (c < MDEN) ? dense_x[r * MDEN + c] : 0.f;
    }
    for (int i = tid; i < 512 * XK; i += stride) {
        int r = i / XK, c = i % XK;
        g_wh[HW0 + i] = __float2half_rn((c < MDEN) ? bw0[r * MDEN + c] : 0.f);
    }
    for (int i = tid; i < 256 * 512; i += stride)
        g_wh[HW1 + i] = __float2half_rn(bw1[i]);
    for (int i = tid; i < 64 * 256; i += stride)
        g_wh[HW2 + i] = __float2half_rn(bw2[i]);
    for (int i = tid; i < 512 * PDIM; i += stride) {
        int r = i / PDIM, c = i % PDIM;
        g_wh[HTW0 + i] = __float2half_rn((c < TOPIN) ? tw0[r * TOPIN + c] : 0.f);
    }
    for (int i = tid; i < 256 * 512; i += stride)
        g_wh[HTW1 + i] = __float2half_rn(tw1[i]);
    for (int i = tid; i < BATCH * (PDIM - TOPIN); i += stride) {
        int r = i / (PDIM - TOPIN), c = TOPIN + i % (PDIM - TOPIN);
        g_scratch[OFF_P + (size_t)r * PDIM + c] = 0.f;
    }
    for (int i = tid; i < BATCH; i += stride)
        out[i] = tb2[0];
}

// ---------------------------------------------------------------------------
// fp16 tensor-core GEMM:  C[M,N] = act(A)[M,K] @ Wh[N,K]^T + bias
// A fp32 (scratch), Wh fp16. CTA 64x64 (4 warps, warp tile 32x32), BK=32.
// A fragments via ldmatrix.x4; B via 32-bit LDS (layouts conflict-free).
// FUSE_FINAL: no C store; instead out[row] += dot(relu(c+bias), w2) (atomic).
// ---------------------------------------------------------------------------
template<int K, bool RELU, bool FUSE_FINAL>
__global__ __launch_bounds__(128)
void mma_gemm_h(int aoff, const __half* __restrict__ Wh,
                const float* __restrict__ bias,
                int coff, int cstride,
                float* __restrict__ outp, const float* __restrict__ w2)
{
    constexpr int BM = 64, BN = 64, BK = 32;
    constexpr int THREADS = 128;
    constexpr int SKA = BK + 8;            // 40 halves (20 words): conflict-free
    constexpr int AF4 = BM*BK/(4*THREADS); // 4 float4 per thread
    constexpr int WU4 = BN*BK/(8*THREADS); // 2 uint4 per thread

    __shared__ __align__(16) __half As[BM][SKA];
    __shared__ __align__(16) __half Ws[BN][SKA];

    const float* A = (const float*)g_scratch + aoff;
    float* C = g_scratch + coff;

    const int tid  = threadIdx.x;
    const int wid  = tid >> 5;
    const int lane = tid & 31;
    const int qr   = lane & 3;
    const int gr   = lane >> 2;
    const int wm0  = (wid >> 1) * 32;
    const int wn0  = (wid & 1) * 32;
    const int m0   = blockIdx.y * BM;
    const int n0   = blockIdx.x * BN;

    // ldmatrix source address (per lane), updated with kk inside loop
    const int lrow = lane & 15, lkof = (lane >> 4) << 3;

    float4 pa[AF4];
    uint4  pw[WU4];
    #pragma unroll
    for (int i = 0; i < AF4; i++) {
        int f = tid + i*THREADS, r = f >> 3, kq = f & 7;
        pa[i] = *(const float4*)&A[(size_t)(m0 + r) * K + kq*4];
    }
    #pragma unroll
    for (int i = 0; i < WU4; i++) {
        int f = tid + i*THREADS, r = f >> 2, q = f & 3;
        pw[i] = *(const uint4*)&Wh[(size_t)(n0 + r) * K + q*8];
    }

    float acc[2][4][4];
    #pragma unroll
    for (int mt = 0; mt < 2; mt++)
        #pragma unroll
        for (int nt = 0; nt < 4; nt++)
            #pragma unroll
            for (int e = 0; e < 4; e++)
                acc[mt][nt][e] = 0.f;

    for (int k0 = 0; k0 < K; k0 += BK) {
        // commit prefetched tiles
        #pragma unroll
        for (int i = 0; i < AF4; i++) {
            int f = tid + i*THREADS, r = f >> 3, kq = f & 7;
            float4 v = pa[i];
            if (RELU) { v.x=fmaxf(v.x,0.f); v.y=fmaxf(v.y,0.f);
                        v.z=fmaxf(v.z,0.f); v.w=fmaxf(v.w,0.f); }
            __half2 h0 = __floats2half2_rn(v.x, v.y);
            __half2 h1 = __floats2half2_rn(v.z, v.w);
            *(__half2*)&As[r][kq*4]     = h0;
            *(__half2*)&As[r][kq*4 + 2] = h1;
        }
        #pragma unroll
        for (int i = 0; i < WU4; i++) {
            int f = tid + i*THREADS, r = f >> 2, q = f & 3;
            *(uint4*)&Ws[r][q*8] = pw[i];
        }
        __syncthreads();

        if (k0 + BK < K) {
            #pragma unroll
            for (int i = 0; i < AF4; i++) {
                int f = tid + i*THREADS, r = f >> 3, kq = f & 7;
                pa[i] = *(const float4*)&A[(size_t)(m0 + r) * K + k0 + BK + kq*4];
            }
            #pragma unroll
            for (int i = 0; i < WU4; i++) {
                int f = tid + i*THREADS, r = f >> 2, q = f & 3;
                pw[i] = *(const uint4*)&Wh[(size_t)(n0 + r) * K + k0 + BK + q*8];
            }
        }

        #pragma unroll
        for (int kk = 0; kk < BK; kk += 16) {
            uint32_t af[2][4];
            #pragma unroll
            for (int mt = 0; mt < 2; mt++) {
                uint32_t addr = smem_u32(&As[wm0 + mt*16 + lrow][kk + lkof]);
                ldm_x4(af[mt], addr);
            }
            uint32_t bf[4][2];
            #pragma unroll
            for (int nt = 0; nt < 4; nt++) {
                int n = wn0 + nt*8 + gr;
                bf[nt][0] = *(const uint32_t*)&Ws[n][kk + 2*qr];
                bf[nt][1] = *(const uint32_t*)&Ws[n][kk + 2*qr + 8];
            }
            #pragma unroll
            for (int mt = 0; mt < 2; mt++)
                #pragma unroll
                for (int nt = 0; nt < 4; nt++)
                    mma_f16(acc[mt][nt], af[mt][0], af[mt][1], af[mt][2], af[mt][3],
                            bf[nt][0], bf[nt][1]);
        }
        __syncthreads();
    }

    if (!FUSE_FINAL) {
        #pragma unroll
        for (int mt = 0; mt < 2; mt++) {
            int row = m0 + wm0 + mt*16 + gr;
            #pragma unroll
            for (int nt = 0; nt < 4; nt++) {
                int col = n0 + wn0 + nt*8 + 2*qr;
                float bx = bias[col], by = bias[col + 1];
                float2 v0 = { acc[mt][nt][0] + bx, acc[mt][nt][1] + by };
                float2 v1 = { acc[mt][nt][2] + bx, acc[mt][nt][3] + by };
                *(float2*)&C[(size_t)row * cstride + col] = v0;
                *(float2*)&C[(size_t)(row + 8) * cstride + col] = v1;
            }
        }
    } else {
        // out[row] += dot(relu(c + bias), w2) over this CTA's 64 cols
        #pragma unroll
        for (int mt = 0; mt < 2; mt++) {
            int r0 = m0 + wm0 + mt*16 + gr;
            float p0 = 0.f, p1 = 0.f;
            #pragma unroll
            for (int nt = 0; nt < 4; nt++) {
                int col = n0 + wn0 + nt*8 + 2*qr;
                float bx = bias[col], by = bias[col + 1];
                float wx = w2[col],  wy = w2[col + 1];
                p0 += fmaxf(acc[mt][nt][0] + bx, 0.f) * wx
                    + fmaxf(acc[mt][nt][1] + by, 0.f) * wy;
                p1 += fmaxf(acc[mt][nt][2] + bx, 0.f) * wx
                    + fmaxf(acc[mt][nt][3] + by, 0.f) * wy;
            }
            p0 += __shfl_xor_sync(0xffffffffu, p0, 1);
            p0 += __shfl_xor_sync(0xffffffffu, p0, 2);
            p1 += __shfl_xor_sync(0xffffffffu, p1, 1);
            p1 += __shfl_xor_sync(0xffffffffu, p1, 2);
            if (qr == 0) {
                atomicAdd(&outp[r0], p0);
                atomicAdd(&outp[r0 + 8], p1);
            }
        }
    }
}

// ---------------------------------------------------------------------------
// Interaction kernel. One warp per batch row; x_bot already in P[b][0:64].
// ---------------------------------------------------------------------------
#define IPAD 28

__global__ __launch_bounds__(128)
void interact_kernel(const int* __restrict__ sidx,
                     const float* __restrict__ emb)
{
    __shared__ __align__(16) float Tt[4][EMBD][IPAD];

    const int w    = threadIdx.x >> 5;
    const int lane = threadIdx.x & 31;
    const int b    = blockIdx.x * 4 + w;

    float* prow = g_scratch + OFF_P + (size_t)b * PDIM;
    float (*T)[IPAD] = Tt[w];

    const float* srcs[NI];
    srcs[0] = prow;
    #pragma unroll
    for (int r = 1; r < NI; r++) {
        int ix = sidx[(size_t)(r - 1) * BATCH + b];
        ix = ix < 0 ? 0 : (ix >= VOCAB ? VOCAB - 1 : ix);
        srcs[r] = emb + ((size_t)(r - 1) * VOCAB + (size_t)ix) * EMBD;
    }
    float2 vbuf[NI];
    #pragma unroll
    for (int r = 0; r < NI; r++)
        vbuf[r] = ((const float2*)srcs[r])[lane];
    #pragma unroll
    for (int r = 0; r < NI; r++) {
        T[2*lane    ][r] = vbuf[r].x;
        T[2*lane + 1][r] = vbuf[r].y;
    }
    __syncwarp();

    if (lane < 28) {
        int ti = 0;
        while ((ti + 1) * (ti + 2) / 2 <= lane) ti++;
        int tj = lane - ti * (ti + 1) / 2;

        float acc[4][4];
        #pragma unroll
        for (int a = 0; a < 4; a++)
            #pragma unroll
            for (int c = 0; c < 4; c++)
                acc[a][c] = 0.f;

        #pragma unroll 8
        for (int k = 0; k < EMBD; k++) {
            float4 av = *(const float4*)&T[k][4*ti];
            float4 bv = *(const float4*)&T[k][4*tj];
            float ra[4] = {av.x, av.y, av.z, av.w};
            float rb[4] = {bv.x, bv.y, bv.z, bv.w};
            #pragma unroll
            for (int a = 0; a < 4; a++)
                #pragma unroll
                for (int c = 0; c < 4; c++)
                    acc[a][c] += ra[a] * rb[c];
        }

        #pragma unroll
        for (int a = 0; a < 4; a++) {
            int i = 4*ti + a;
            #pragma unroll
            for (int c = 0; c < 4; c++) {
                int j = 4*tj + c;
                if (i < NI && j < i)
                    prow[EMBD + i*(i-1)/2 + j] = acc[a][c];
            }
        }
    }
}

// ---------------------------------------------------------------------------
// Launch sequence
// ---------------------------------------------------------------------------
extern "C" void kernel_launch(void* const* d_in, const int* in_sizes, int n_in,
                              void* d_out, int out_size)
{
    const float* dense_x = (const float*)d_in[0];
    const int*   sidx    = (const int*)d_in[1];
    const float* emb     = (const float*)d_in[2];
    const float* bw0 = (const float*)d_in[3];
    const float* bb0 = (const float*)d_in[4];
    const float* bw1 = (const float*)d_in[5];
    const float* bb1 = (const float*)d_in[6];
    const float* bw2 = (const float*)d_in[7];
    const float* bb2 = (const float*)d_in[8];
    const float* tw0 = (const float*)d_in[9];
    const float* tb0 = (const float*)d_in[10];
    const float* tw1 = (const float*)d_in[11];
    const float* tb1 = (const float*)d_in[12];
    const float* tw2 = (const float*)d_in[13];
    const float* tb2 = (const float*)d_in[14];
    float* out = (float*)d_out;

    __half* wh;
    cudaGetSymbolAddress((void**)&wh, g_wh);

    prep_kernel<<<256, 256>>>(dense_x, bw0, bw1, bw2, tw0, tw1, tb2, out);

    // bot-L0: XPAD[4096,32] @ W0h[512,32]^T -> H1
    mma_gemm_h<XK, false, false><<<dim3(512/64, BATCH/64), 128>>>(
        OFF_XPAD, wh + HW0, bb0, OFF_H1, 512, nullptr, nullptr);
    // bot-L1: relu(H1) @ W1h[256,512]^T -> H2
    mma_gemm_h<512, true, false><<<dim3(256/64, BATCH/64), 128>>>(
        OFF_H1, wh + HW1, bb1, OFF_H2, 256, nullptr, nullptr);
    // bot-L2: relu(H2) @ W2h[64,256]^T -> P[:,0:64] (stride 512)
    mma_gemm_h<256, true, false><<<dim3(1, BATCH/64), 128>>>(
        OFF_H2, wh + HW2, bb2, OFF_P, PDIM, nullptr, nullptr);

    // gather + interaction -> P[:,64:415]
    interact_kernel<<<BATCH/4, 128>>>(sidx, emb);

    // top-L0: P[4096,512] @ TW0h[512,512]^T -> T1
    mma_gemm_h<PDIM, false, false><<<dim3(512/64, BATCH/64), 128>>>(
        OFF_P, wh + HTW0, tb0, OFF_T1, 512, nullptr, nullptr);
    // top-L1 + final fused: out[b] (+)= dot(relu(relu(T1)@TW1h^T + tb1), tw2)
    mma_gemm_h<512, true, true><<<dim3(256/64, BATCH/64), 128>>>(
        OFF_T1, wh + HTW1, tb1, 0, 0, out, tw2);
}

// round 8
// speedup vs baseline: 4.9675x; 1.0547x over previous
#include <cuda_runtime.h>
#include <cuda_fp16.h>
#include <cstdint>
#include <math.h>

// ---------------------------------------------------------------------------
// DLRM forward, 4 launches:
//   prep -> bottom_mlp (fused 3-layer) -> interact -> top_mlp (fused 3-layer)
// GEMMs: mma.sync m16n8k16 fp16 (fp32 accum). Activations live in SMEM.
// ---------------------------------------------------------------------------

#define BATCH   4096
#define MDEN    13
#define NI      27
#define EMBD    64
#define VOCAB   100000
#define TOPIN   415
#define PDIM    512

// fp32 scratch: only P survives in global
#define OFF_P    0
#define SCRATCH_TOTAL (BATCH*PDIM)
__device__ __align__(16) float g_scratch[SCRATCH_TOTAL];

// fp16 weights
#define HW0   0                     // [512,32]  (bw0 zero-padded 13->32)
#define HW1   (HW0  + 512*32)       // [256,512]
#define HW2   (HW1  + 256*512)      // [64,256]
#define HTW0  (HW2  + 64*256)       // [512,512] (tw0 zero-padded 415->512)
#define HTW1  (HTW0 + 512*512)      // [256,512]
#define HTOTAL (HTW1 + 256*512)
__device__ __align__(16) __half g_wh[HTOTAL];

__device__ __forceinline__ uint32_t smem_u32(const void* p) {
    uint32_t a;
    asm("{ .reg .u64 t; cvta.to.shared.u64 t, %1; cvt.u32.u64 %0, t; }"
        : "=r"(a) : "l"(p));
    return a;
}
__device__ __forceinline__ void mma_f16(float* c, uint32_t a0, uint32_t a1,
                                        uint32_t a2, uint32_t a3,
                                        uint32_t b0, uint32_t b1) {
    asm volatile(
        "mma.sync.aligned.m16n8k16.row.col.f32.f16.f16.f32 "
        "{%0,%1,%2,%3}, {%4,%5,%6,%7}, {%8,%9}, {%0,%1,%2,%3};"
        : "+f"(c[0]), "+f"(c[1]), "+f"(c[2]), "+f"(c[3])
        : "r"(a0), "r"(a1), "r"(a2), "r"(a3), "r"(b0), "r"(b1));
}
__device__ __forceinline__ void ldm_x4(uint32_t* r, uint32_t addr) {
    asm volatile("ldmatrix.sync.aligned.m8n8.x4.shared.b16 {%0,%1,%2,%3}, [%4];"
                 : "=r"(r[0]), "=r"(r[1]), "=r"(r[2]), "=r"(r[3]) : "r"(addr));
}

// ---------------------------------------------------------------------------
// Prep: convert/pad weights to fp16; zero P pad cols.
// ---------------------------------------------------------------------------
__global__ void prep_kernel(const float* __restrict__ bw0,
                            const float* __restrict__ bw1,
                            const float* __restrict__ bw2,
                            const float* __restrict__ tw0,
                            const float* __restrict__ tw1)
{
    int tid = blockIdx.x * blockDim.x + threadIdx.x;
    int stride = gridDim.x * blockDim.x;

    for (int i = tid; i < 512 * 32; i += stride) {
        int r = i >> 5, c = i & 31;
        g_wh[HW0 + i] = __float2half_rn((c < MDEN) ? bw0[r * MDEN + c] : 0.f);
    }
    for (int i = tid; i < 256 * 512; i += stride)
        g_wh[HW1 + i] = __float2half_rn(bw1[i]);
    for (int i = tid; i < 64 * 256; i += stride)
        g_wh[HW2 + i] = __float2half_rn(bw2[i]);
    for (int i = tid; i < 512 * 512; i += stride) {
        int r = i >> 9, c = i & 511;
        g_wh[HTW0 + i] = __float2half_rn((c < TOPIN) ? tw0[r * TOPIN + c] : 0.f);
    }
    for (int i = tid; i < 256 * 512; i += stride)
        g_wh[HTW1 + i] = __float2half_rn(tw1[i]);
    for (int i = tid; i < BATCH * (PDIM - TOPIN); i += stride) {
        int r = i / (PDIM - TOPIN), c = TOPIN + i % (PDIM - TOPIN);
        g_scratch[OFF_P + (size_t)r * PDIM + c] = 0.f;
    }
}

// ---------------------------------------------------------------------------
// Streamed-W stage: Ds[32][NOUT] = relu( As[32][512] @ Wg[NOUT,512]^T + bias )
// 256 threads / 8 warps: warp (wid>>2) -> m16 group, (wid&3) -> 32-col group.
// W streamed in [128 x 64] fp16 chunks, double-buffered smem + reg staging.
// ---------------------------------------------------------------------------
template<int NOUT, int DSTRIDE>
__device__ __forceinline__ void stage_stream(
    const __half (*As)[520],
    __half (*Wc)[72],                 // [256][72] : buf*128 + row
    const __half* __restrict__ Wg,    // [NOUT, 512]
    const float* __restrict__ bias,
    __half (*Ds)[DSTRIDE])
{
    const int tid  = threadIdx.x;
    const int lane = tid & 31, wid = tid >> 5;
    const int qr   = lane & 3, gr = lane >> 2;
    const int wm0  = (wid >> 2) * 16, wng = wid & 3;
    const int lrow = lane & 15, lkof = (lane >> 4) << 3;

    #pragma unroll 1
    for (int nb = 0; nb < NOUT / 128; nb++) {
        const __half* Wn = Wg + (size_t)(nb * 128) * 512;

        uint4 st[4];
        #pragma unroll
        for (int j = 0; j < 4; j++) {
            int f = tid + j * 256, r = f >> 3, c = (f & 7) * 8;
            st[j] = *(const uint4*)&Wn[(size_t)r * 512 + c];
        }
        #pragma unroll
        for (int j = 0; j < 4; j++) {
            int f = tid + j * 256, r = f >> 3, c = (f & 7) * 8;
            *(uint4*)&Wc[r][c] = st[j];
        }
        __syncthreads();

        float acc[4][4];
        #pragma unroll
        for (int nt = 0; nt < 4; nt++)
            #pragma unroll
            for (int e = 0; e < 4; e++)
                acc[nt][e] = 0.f;

        #pragma unroll 1
        for (int kc = 0; kc < 8; kc++) {
            if (kc < 7) {
                #pragma unroll
                for (int j = 0; j < 4; j++) {
                    int f = tid + j * 256, r = f >> 3, c = (f & 7) * 8;
                    st[j] = *(const uint4*)&Wn[(size_t)r * 512 + (kc + 1) * 64 + c];
                }
            }
            const __half (*Wb)[72] = Wc + (kc & 1) * 128;
            #pragma unroll
            for (int kk = 0; kk < 64; kk += 16) {
                uint32_t af[4];
                ldm_x4(af, smem_u32(&As[wm0 + lrow][kc * 64 + kk + lkof]));
                #pragma unroll
                for (int nt = 0; nt < 4; nt++) {
                    int n = wng * 32 + nt * 8 + gr;
                    uint32_t b0 = *(const uint32_t*)&Wb[n][kk + 2 * qr];
                    uint32_t b1 = *(const uint32_t*)&Wb[n][kk + 2 * qr + 8];
                    mma_f16(acc[nt], af[0], af[1], af[2], af[3], b0, b1);
                }
            }
            if (kc < 7) {
                #pragma unroll
                for (int j = 0; j < 4; j++) {
                    int f = tid + j * 256, r = f >> 3, c = (f & 7) * 8;
                    *(uint4*)&Wc[((kc + 1) & 1) * 128 + r][c] = st[j];
                }
            }
            __syncthreads();
        }

        // epilogue: bias + relu -> Ds (fp16)
        #pragma unroll
        for (int nt = 0; nt < 4; nt++) {
            int col = nb * 128 + wng * 32 + nt * 8 + 2 * qr;
            float bx = bias[col], by = bias[col + 1];
            float v0 = fmaxf(acc[nt][0] + bx, 0.f), v1 = fmaxf(acc[nt][1] + by, 0.f);
            float v2 = fmaxf(acc[nt][2] + bx, 0.f), v3 = fmaxf(acc[nt][3] + by, 0.f);
            *(__half2*)&Ds[wm0 + gr][col]     = __floats2half2_rn(v0, v1);
            *(__half2*)&Ds[wm0 + gr + 8][col] = __floats2half2_rn(v2, v3);
        }
        __syncthreads();
    }
}

// ---------------------------------------------------------------------------
// Bottom MLP megakernel: 32 batch rows / CTA, grid 128.
//   A: H1 = relu(dense @ W0^T + bb0)      (K=32, W0 smem-resident)
//   B: H2 = relu(H1 @ W1^T + bb1)         (K=512, W1 streamed)
//   C: x_bot = H2 @ W2^T + bb2 -> P[:,0:64]  (K=256, W2 smem-resident)
// ---------------------------------------------------------------------------
#define BOT_SMEM 164352
__global__ __launch_bounds__(256)
void bottom_mlp(const float* __restrict__ dense_x,
                const __half* __restrict__ W0h,
                const __half* __restrict__ W1h,
                const __half* __restrict__ W2h,
                const float* __restrict__ bb0,
                const float* __restrict__ bb1,
                const float* __restrict__ bb2)
{
    extern __shared__ __align__(16) char smem[];
    __half (*Xs)[40]   = (__half(*)[40] )(smem + 0);       //  2560 B
    __half (*W0s)[40]  = (__half(*)[40] )(smem + 2560);    // 40960 B
    __half (*H1s)[520] = (__half(*)[520])(smem + 43520);   // 33280 B
    __half (*Wc)[72]   = (__half(*)[72] )(smem + 76800);   // 36864 B
    __half (*H2s)[264] = (__half(*)[264])(smem + 113664);  // 16896 B
    __half (*W2s)[264] = (__half(*)[264])(smem + 130560);  // 33792 B

    const int tid  = threadIdx.x;
    const int lane = tid & 31, wid = tid >> 5;
    const int qr   = lane & 3, gr = lane >> 2;
    const int wm0  = (wid >> 2) * 16, wng = wid & 3;
    const int lrow = lane & 15, lkof = (lane >> 4) << 3;
    const int m0   = blockIdx.x * 32;

    // ---- loads ----
    for (int i = tid; i < 32 * MDEN; i += 256) {
        int r = i / MDEN, c = i % MDEN;
        Xs[r][c] = __float2half_rn(dense_x[(size_t)(m0 + r) * MDEN + c]);
    }
    for (int i = tid; i < 32 * (32 - MDEN); i += 256) {
        int r = i / (32 - MDEN), c = MDEN + i % (32 - MDEN);
        Xs[r][c] = __float2half_rn(0.f);
    }
    #pragma unroll
    for (int j = 0; j < 8; j++) {                    // W0s: 512x32 halves
        int f = tid + j * 256, r = f >> 2, c = (f & 3) * 8;
        *(uint4*)&W0s[r][c] = *(const uint4*)&W0h[r * 32 + c];
    }
    #pragma unroll
    for (int j = 0; j < 8; j++) {                    // W2s: 64x256 halves
        int f = tid + j * 256, r = f >> 5, c = (f & 31) * 8;
        *(uint4*)&W2s[r][c] = *(const uint4*)&W2h[r * 256 + c];
    }
    __syncthreads();

    // ---- stage A: K=32, out 32x512 -> H1s (relu) ----
    #pragma unroll 1
    for (int nb = 0; nb < 4; nb++) {
        float acc[4][4];
        #pragma unroll
        for (int nt = 0; nt < 4; nt++)
            #pragma unroll
            for (int e = 0; e < 4; e++)
                acc[nt][e] = 0.f;
        #pragma unroll
        for (int kk = 0; kk < 32; kk += 16) {
            uint32_t af[4];
            ldm_x4(af, smem_u32(&Xs[wm0 + lrow][kk + lkof]));
            #pragma unroll
            for (int nt = 0; nt < 4; nt++) {
                int n = nb * 128 + wng * 32 + nt * 8 + gr;
                uint32_t b0 = *(const uint32_t*)&W0s[n][kk + 2 * qr];
                uint32_t b1 = *(const uint32_t*)&W0s[n][kk + 2 * qr + 8];
                mma_f16(acc[nt], af[0], af[1], af[2], af[3], b0, b1);
            }
        }
        #pragma unroll
        for (int nt = 0; nt < 4; nt++) {
            int col = nb * 128 + wng * 32 + nt * 8 + 2 * qr;
            float bx = bb0[col], by = bb0[col + 1];
            float v0 = fmaxf(acc[nt][0] + bx, 0.f), v1 = fmaxf(acc[nt][1] + by, 0.f);
            float v2 = fmaxf(acc[nt][2] + bx, 0.f), v3 = fmaxf(acc[nt][3] + by, 0.f);
            *(__half2*)&H1s[wm0 + gr][col]     = __floats2half2_rn(v0, v1);
            *(__half2*)&H1s[wm0 + gr + 8][col] = __floats2half2_rn(v2, v3);
        }
    }
    __syncthreads();

    // ---- stage B: K=512 streamed, out 32x256 -> H2s (relu) ----
    stage_stream<256, 264>(H1s, Wc, W1h, bb1, H2s);
    __syncthreads();

    // ---- stage C: K=256, out 32x64 -> P[:,0:64] (no relu) ----
    {
        float acc[2][4];
        #pragma unroll
        for (int nt = 0; nt < 2; nt++)
            #pragma unroll
            for (int e = 0; e < 4; e++)
                acc[nt][e] = 0.f;
        #pragma unroll 4
        for (int kk = 0; kk < 256; kk += 16) {
            uint32_t af[4];
            ldm_x4(af, smem_u32(&H2s[wm0 + lrow][kk + lkof]));
            #pragma unroll
            for (int nt = 0; nt < 2; nt++) {
                int n = wng * 16 + nt * 8 + gr;
                uint32_t b0 = *(const uint32_t*)&W2s[n][kk + 2 * qr];
                uint32_t b1 = *(const uint32_t*)&W2s[n][kk + 2 * qr + 8];
                mma_f16(acc[nt], af[0], af[1], af[2], af[3], b0, b1);
            }
        }
        float* P = g_scratch + OFF_P;
        #pragma unroll
        for (int nt = 0; nt < 2; nt++) {
            int col = wng * 16 + nt * 8 + 2 * qr;
            float bx = bb2[col], by = bb2[col + 1];
            float2 v0 = { acc[nt][0] + bx, acc[nt][1] + by };
            float2 v1 = { acc[nt][2] + bx, acc[nt][3] + by };
            *(float2*)&P[(size_t)(m0 + wm0 + gr) * PDIM + col]     = v0;
            *(float2*)&P[(size_t)(m0 + wm0 + gr + 8) * PDIM + col] = v1;
        }
    }
}

// ---------------------------------------------------------------------------
// Top MLP megakernel: 32 batch rows / CTA, grid 128.
//   A: T1 = relu(P @ TW0^T + tb0)     (K=512 streamed)
//   B: T2 = relu(T1 @ TW1^T + tb1)    (K=512 streamed)
//   C: out = T2 . tw2 + tb2           (SIMT dot, 8 threads/row)
// ---------------------------------------------------------------------------
#define TOP_SMEM 120320
__global__ __launch_bounds__(256)
void top_mlp(const __half* __restrict__ TW0h,
             const __half* __restrict__ TW1h,
             const float* __restrict__ tb0,
             const float* __restrict__ tb1,
             const float* __restrict__ tw2,
             const float* __restrict__ tb2,
             float* __restrict__ out)
{
    extern __shared__ __align__(16) char smem[];
    __half (*Xs)[520]  = (__half(*)[520])(smem + 0);       // 33280 B
    __half (*H1s)[520] = (__half(*)[520])(smem + 33280);   // 33280 B
    __half (*Wc)[72]   = (__half(*)[72] )(smem + 66560);   // 36864 B
    __half (*H2s)[264] = (__half(*)[264])(smem + 103424);  // 16896 B

    const int tid = threadIdx.x;
    const int m0  = blockIdx.x * 32;

    // load P rows -> fp16
    const float* Pr = g_scratch + OFF_P + (size_t)m0 * PDIM;
    #pragma unroll
    for (int j = 0; j < 16; j++) {
        int f = tid + j * 256, r = f >> 7, cq = f & 127;
        float4 v = *(const float4*)&Pr[(size_t)r * PDIM + cq * 4];
        *(__half2*)&Xs[r][cq * 4]     = __floats2half2_rn(v.x, v.y);
        *(__half2*)&Xs[r][cq * 4 + 2] = __floats2half2_rn(v.z, v.w);
    }
    __syncthreads();

    stage_stream<512, 520>(Xs, Wc, TW0h, tb0, H1s);
    __syncthreads();
    stage_stream<256, 264>(H1s, Wc, TW1h, tb1, H2s);
    __syncthreads();

    // final dot: 8 threads per row
    {
        int r = tid >> 3, part = tid & 7;
        float s = 0.f;
        #pragma unroll
        for (int c = 0; c < 32; c++) {
            int col = part * 32 + c;
            s += __half2float(H2s[r][col]) * tw2[col];
        }
        s += __shfl_xor_sync(0xffffffffu, s, 1);
        s += __shfl_xor_sync(0xffffffffu, s, 2);
        s += __shfl_xor_sync(0xffffffffu, s, 4);
        if (part == 0) out[m0 + r] = s + tb2[0];
    }
}

// ---------------------------------------------------------------------------
// Interaction kernel. One warp per batch row; x_bot already in P[b][0:64].
// ---------------------------------------------------------------------------
#define IPAD 28

__global__ __launch_bounds__(128)
void interact_kernel(const int* __restrict__ sidx,
                     const float* __restrict__ emb)
{
    __shared__ __align__(16) float Tt[4][EMBD][IPAD];

    const int w    = threadIdx.x >> 5;
    const int lane = threadIdx.x & 31;
    const int b    = blockIdx.x * 4 + w;

    float* prow = g_scratch + OFF_P + (size_t)b * PDIM;
    float (*T)[IPAD] = Tt[w];

    const float* srcs[NI];
    srcs[0] = prow;
    #pragma unroll
    for (int r = 1; r < NI; r++) {
        int ix = sidx[(size_t)(r - 1) * BATCH + b];
        ix = ix < 0 ? 0 : (ix >= VOCAB ? VOCAB - 1 : ix);
        srcs[r] = emb + ((size_t)(r - 1) * VOCAB + (size_t)ix) * EMBD;
    }
    float2 vbuf[NI];
    #pragma unroll
    for (int r = 0; r < NI; r++)
        vbuf[r] = ((const float2*)srcs[r])[lane];
    #pragma unroll
    for (int r = 0; r < NI; r++) {
        T[2*lane    ][r] = vbuf[r].x;
        T[2*lane + 1][r] = vbuf[r].y;
    }
    __syncwarp();

    if (lane < 28) {
        int ti = 0;
        while ((ti + 1) * (ti + 2) / 2 <= lane) ti++;
        int tj = lane - ti * (ti + 1) / 2;

        float acc[4][4];
        #pragma unroll
        for (int a = 0; a < 4; a++)
            #pragma unroll
            for (int c = 0; c < 4; c++)
                acc[a][c] = 0.f;

        #pragma unroll 8
        for (int k = 0; k < EMBD; k++) {
            float4 av = *(const float4*)&T[k][4*ti];
            float4 bv = *(const float4*)&T[k][4*tj];
            float ra[4] = {av.x, av.y, av.z, av.w};
            float rb[4] = {bv.x, bv.y, bv.z, bv.w};
            #pragma unroll
            for (int a = 0; a < 4; a++)
                #pragma unroll
                for (int c = 0; c < 4; c++)
                    acc[a][c] += ra[a] * rb[c];
        }

        #pragma unroll
        for (int a = 0; a < 4; a++) {
            int i = 4*ti + a;
            #pragma unroll
            for (int c = 0; c < 4; c++) {
                int j = 4*tj + c;
                if (i < NI && j < i)
                    prow[EMBD + i*(i-1)/2 + j] = acc[a][c];
            }
        }
    }
}

// ---------------------------------------------------------------------------
// Launch sequence
// ---------------------------------------------------------------------------
extern "C" void kernel_launch(void* const* d_in, const int* in_sizes, int n_in,
                              void* d_out, int out_size)
{
    const float* dense_x = (const float*)d_in[0];
    const int*   sidx    = (const int*)d_in[1];
    const float* emb     = (const float*)d_in[2];
    const float* bw0 = (const float*)d_in[3];
    const float* bb0 = (const float*)d_in[4];
    const float* bw1 = (const float*)d_in[5];
    const float* bb1 = (const float*)d_in[6];
    const float* bw2 = (const float*)d_in[7];
    const float* bb2 = (const float*)d_in[8];
    const float* tw0 = (const float*)d_in[9];
    const float* tb0 = (const float*)d_in[10];
    const float* tw1 = (const float*)d_in[11];
    const float* tb1 = (const float*)d_in[12];
    const float* tw2 = (const float*)d_in[13];
    const float* tb2 = (const float*)d_in[14];
    float* out = (float*)d_out;

    __half* wh;
    cudaGetSymbolAddress((void**)&wh, g_wh);

    cudaFuncSetAttribute(bottom_mlp, cudaFuncAttributeMaxDynamicSharedMemorySize, BOT_SMEM);
    cudaFuncSetAttribute(top_mlp,    cudaFuncAttributeMaxDynamicSharedMemorySize, TOP_SMEM);

    prep_kernel<<<256, 256>>>(bw0, bw1, bw2, tw0, tw1);

    bottom_mlp<<<BATCH/32, 256, BOT_SMEM>>>(dense_x, wh + HW0, wh + HW1, wh + HW2,
                                            bb0, bb1, bb2);

    interact_kernel<<<BATCH/4, 128>>>(sidx, emb);

    top_mlp<<<BATCH/32, 256, TOP_SMEM>>>(wh + HTW0, wh + HTW1,
                                         tb0, tb1, tw2, tb2, out);
}

// round 9
// speedup vs baseline: 5.1188x; 1.0305x over previous
#include <cuda_runtime.h>
#include <cuda_fp16.h>
#include <cstdint>
#include <math.h>

// ---------------------------------------------------------------------------
// DLRM forward, 4 launches:
//   prep -> bottom_mlp (fused 3-layer) -> interact -> top_mlp (fused 3-layer)
// GEMMs: mma.sync m16n8k16 fp16 (fp32 accum). Weight streaming via cp.async
// 4-buffer pipeline (2 chunks in flight). Activations live in SMEM.
// ---------------------------------------------------------------------------

#define BATCH   4096
#define MDEN    13
#define NI      27
#define EMBD    64
#define VOCAB   100000
#define TOPIN   415
#define PDIM    512

// fp32 scratch: only P survives in global
#define OFF_P    0
#define SCRATCH_TOTAL (BATCH*PDIM)
__device__ __align__(16) float g_scratch[SCRATCH_TOTAL];

// fp16 weights
#define HW0   0                     // [512,32]  (bw0 zero-padded 13->32)
#define HW1   (HW0  + 512*32)       // [256,512]
#define HW2   (HW1  + 256*512)      // [64,256]
#define HTW0  (HW2  + 64*256)       // [512,512] (tw0 zero-padded 415->512)
#define HTW1  (HTW0 + 512*512)      // [256,512]
#define HTOTAL (HTW1 + 256*512)
__device__ __align__(16) __half g_wh[HTOTAL];

__device__ __forceinline__ uint32_t smem_u32(const void* p) {
    uint32_t a;
    asm("{ .reg .u64 t; cvta.to.shared.u64 t, %1; cvt.u32.u64 %0, t; }"
        : "=r"(a) : "l"(p));
    return a;
}
__device__ __forceinline__ void mma_f16(float* c, uint32_t a0, uint32_t a1,
                                        uint32_t a2, uint32_t a3,
                                        uint32_t b0, uint32_t b1) {
    asm volatile(
        "mma.sync.aligned.m16n8k16.row.col.f32.f16.f16.f32 "
        "{%0,%1,%2,%3}, {%4,%5,%6,%7}, {%8,%9}, {%0,%1,%2,%3};"
        : "+f"(c[0]), "+f"(c[1]), "+f"(c[2]), "+f"(c[3])
        : "r"(a0), "r"(a1), "r"(a2), "r"(a3), "r"(b0), "r"(b1));
}
__device__ __forceinline__ void ldm_x4(uint32_t* r, uint32_t addr) {
    asm volatile("ldmatrix.sync.aligned.m8n8.x4.shared.b16 {%0,%1,%2,%3}, [%4];"
                 : "=r"(r[0]), "=r"(r[1]), "=r"(r[2]), "=r"(r[3]) : "r"(addr));
}
__device__ __forceinline__ void cp16(uint32_t saddr, const void* g) {
    asm volatile("cp.async.cg.shared.global [%0], [%1], 16;" :: "r"(saddr), "l"(g));
}
#define CP_COMMIT() asm volatile("cp.async.commit_group;" ::: "memory")

// ---------------------------------------------------------------------------
// Prep: convert/pad weights to fp16; zero P pad cols.
// ---------------------------------------------------------------------------
__global__ void prep_kernel(const float* __restrict__ bw0,
                            const float* __restrict__ bw1,
                            const float* __restrict__ bw2,
                            const float* __restrict__ tw0,
                            const float* __restrict__ tw1)
{
    int tid = blockIdx.x * blockDim.x + threadIdx.x;
    int stride = gridDim.x * blockDim.x;

    for (int i = tid; i < 512 * 32; i += stride) {
        int r = i >> 5, c = i & 31;
        g_wh[HW0 + i] = __float2half_rn((c < MDEN) ? bw0[r * MDEN + c] : 0.f);
    }
    for (int i = tid; i < 256 * 512; i += stride)
        g_wh[HW1 + i] = __float2half_rn(bw1[i]);
    for (int i = tid; i < 64 * 256; i += stride)
        g_wh[HW2 + i] = __float2half_rn(bw2[i]);
    for (int i = tid; i < 512 * 512; i += stride) {
        int r = i >> 9, c = i & 511;
        g_wh[HTW0 + i] = __float2half_rn((c < TOPIN) ? tw0[r * TOPIN + c] : 0.f);
    }
    for (int i = tid; i < 256 * 512; i += stride)
        g_wh[HTW1 + i] = __float2half_rn(tw1[i]);
    for (int i = tid; i < BATCH * (PDIM - TOPIN); i += stride) {
        int r = i / (PDIM - TOPIN), c = TOPIN + i % (PDIM - TOPIN);
        g_scratch[OFF_P + (size_t)r * PDIM + c] = 0.f;
    }
}

// ---------------------------------------------------------------------------
// Streamed-W stage: Ds[32][NOUT] = relu( As[32][512] @ Wg[NOUT,512]^T + bias )
// W streamed in [128 n x 64 k] fp16 chunks via cp.async, 4 smem buffers,
// 2 chunks in flight, ONE __syncthreads per chunk.
// 256 threads / 8 warps: warp (wid>>2) -> m16 group, (wid&3) -> 32-col group.
// ---------------------------------------------------------------------------
template<int NOUT, int DSTRIDE>
__device__ __forceinline__ void stage_stream(
    const __half (*As)[520],
    __half (*Wc)[72],                 // [4*128][72]
    const __half* __restrict__ Wg,    // [NOUT, 512]
    const float* __restrict__ bias,
    __half (*Ds)[DSTRIDE])
{
    const int tid  = threadIdx.x;
    const int lane = tid & 31, wid = tid >> 5;
    const int qr   = lane & 3, gr = lane >> 2;
    const int wm0  = (wid >> 2) * 16, wng = wid & 3;
    const int lrow = lane & 15, lkof = (lane >> 4) << 3;
    constexpr int NC = (NOUT / 128) * 8;

    // chunk g: nb = g>>3 (n-block of 128), kc = g&7 (k-chunk of 64)
    auto issue = [&](int g) {
        int nb = g >> 3, kc = g & 7;
        const __half* src = Wg + (size_t)(nb * 128) * 512 + kc * 64;
        __half (*buf)[72] = Wc + (g & 3) * 128;
        #pragma unroll
        for (int j = 0; j < 4; j++) {
            int f = tid + j * 256, r = f >> 3, c = (f & 7) * 8;
            cp16(smem_u32(&buf[r][c]), src + (size_t)r * 512 + c);
        }
        CP_COMMIT();
    };

    issue(0);
    if (NC > 1) issue(1);

    float acc[4][4];
    #pragma unroll
    for (int nt = 0; nt < 4; nt++)
        #pragma unroll
        for (int e = 0; e < 4; e++)
            acc[nt][e] = 0.f;

    #pragma unroll 1
    for (int g = 0; g < NC; g++) {
        if (g + 2 < NC) issue(g + 2);

        int rem = NC - 1 - g;
        if (rem >= 2)      asm volatile("cp.async.wait_group 2;" ::: "memory");
        else if (rem == 1) asm volatile("cp.async.wait_group 1;" ::: "memory");
        else               asm volatile("cp.async.wait_group 0;" ::: "memory");
        __syncthreads();

        const __half (*Wb)[72] = Wc + (g & 3) * 128;
        const int kc = g & 7;

        #pragma unroll
        for (int kk = 0; kk < 64; kk += 16) {
            uint32_t af[4];
            ldm_x4(af, smem_u32(&As[wm0 + lrow][kc * 64 + kk + lkof]));
            #pragma unroll
            for (int nt = 0; nt < 4; nt++) {
                int n = wng * 32 + nt * 8 + gr;
                uint32_t b0 = *(const uint32_t*)&Wb[n][kk + 2 * qr];
                uint32_t b1 = *(const uint32_t*)&Wb[n][kk + 2 * qr + 8];
                mma_f16(acc[nt], af[0], af[1], af[2], af[3], b0, b1);
            }
        }

        if (kc == 7) {
            int nb = g >> 3;
            #pragma unroll
            for (int nt = 0; nt < 4; nt++) {
                int col = nb * 128 + wng * 32 + nt * 8 + 2 * qr;
                float bx = bias[col], by = bias[col + 1];
                float v0 = fmaxf(acc[nt][0] + bx, 0.f), v1 = fmaxf(acc[nt][1] + by, 0.f);
                float v2 = fmaxf(acc[nt][2] + bx, 0.f), v3 = fmaxf(acc[nt][3] + by, 0.f);
                *(__half2*)&Ds[wm0 + gr][col]     = __floats2half2_rn(v0, v1);
                *(__half2*)&Ds[wm0 + gr + 8][col] = __floats2half2_rn(v2, v3);
                #pragma unroll
                for (int e = 0; e < 4; e++) acc[nt][e] = 0.f;
            }
        }
    }
}

// ---------------------------------------------------------------------------
// Bottom MLP megakernel: 32 batch rows / CTA, grid 128.
//   A: H1 = relu(dense @ W0^T + bb0)      (K=32, W0 smem-resident)
//   B: H2 = relu(H1 @ W1^T + bb1)         (K=512, W1 streamed cp.async)
//   C: x_bot = H2 @ W2^T + bb2 -> P[:,0:64]  (K=256, W2 smem-resident)
// ---------------------------------------------------------------------------
#define BOT_SMEM 201216
__global__ __launch_bounds__(256)
void bottom_mlp(const float* __restrict__ dense_x,
                const __half* __restrict__ W0h,
                const __half* __restrict__ W1h,
                const __half* __restrict__ W2h,
                const float* __restrict__ bb0,
                const float* __restrict__ bb1,
                const float* __restrict__ bb2)
{
    extern __shared__ __align__(16) char smem[];
    __half (*Xs)[40]   = (__half(*)[40] )(smem + 0);       //  2560 B
    __half (*W0s)[40]  = (__half(*)[40] )(smem + 2560);    // 40960 B
    __half (*H1s)[520] = (__half(*)[520])(smem + 43520);   // 33280 B
    __half (*Wc)[72]   = (__half(*)[72] )(smem + 76800);   // 73728 B (4 bufs)
    __half (*H2s)[264] = (__half(*)[264])(smem + 150528);  // 16896 B
    __half (*W2s)[264] = (__half(*)[264])(smem + 167424);  // 33792 B

    const int tid  = threadIdx.x;
    const int lane = tid & 31, wid = tid >> 5;
    const int qr   = lane & 3, gr = lane >> 2;
    const int wm0  = (wid >> 2) * 16, wng = wid & 3;
    const int lrow = lane & 15, lkof = (lane >> 4) << 3;
    const int m0   = blockIdx.x * 32;

    // ---- loads ----
    for (int i = tid; i < 32 * MDEN; i += 256) {
        int r = i / MDEN, c = i % MDEN;
        Xs[r][c] = __float2half_rn(dense_x[(size_t)(m0 + r) * MDEN + c]);
    }
    for (int i = tid; i < 32 * (32 - MDEN); i += 256) {
        int r = i / (32 - MDEN), c = MDEN + i % (32 - MDEN);
        Xs[r][c] = __float2half_rn(0.f);
    }
    #pragma unroll
    for (int j = 0; j < 8; j++) {                    // W0s: 512x32 halves
        int f = tid + j * 256, r = f >> 2, c = (f & 3) * 8;
        *(uint4*)&W0s[r][c] = *(const uint4*)&W0h[r * 32 + c];
    }
    #pragma unroll
    for (int j = 0; j < 8; j++) {                    // W2s: 64x256 halves
        int f = tid + j * 256, r = f >> 5, c = (f & 31) * 8;
        *(uint4*)&W2s[r][c] = *(const uint4*)&W2h[r * 256 + c];
    }
    __syncthreads();

    // ---- stage A: K=32, out 32x512 -> H1s (relu) ----
    #pragma unroll 1
    for (int nb = 0; nb < 4; nb++) {
        float acc[4][4];
        #pragma unroll
        for (int nt = 0; nt < 4; nt++)
            #pragma unroll
            for (int e = 0; e < 4; e++)
                acc[nt][e] = 0.f;
        #pragma unroll
        for (int kk = 0; kk < 32; kk += 16) {
            uint32_t af[4];
            ldm_x4(af, smem_u32(&Xs[wm0 + lrow][kk + lkof]));
            #pragma unroll
            for (int nt = 0; nt < 4; nt++) {
                int n = nb * 128 + wng * 32 + nt * 8 + gr;
                uint32_t b0 = *(const uint32_t*)&W0s[n][kk + 2 * qr];
                uint32_t b1 = *(const uint32_t*)&W0s[n][kk + 2 * qr + 8];
                mma_f16(acc[nt], af[0], af[1], af[2], af[3], b0, b1);
            }
        }
        #pragma unroll
        for (int nt = 0; nt < 4; nt++) {
            int col = nb * 128 + wng * 32 + nt * 8 + 2 * qr;
            float bx = bb0[col], by = bb0[col + 1];
            float v0 = fmaxf(acc[nt][0] + bx, 0.f), v1 = fmaxf(acc[nt][1] + by, 0.f);
            float v2 = fmaxf(acc[nt][2] + bx, 0.f), v3 = fmaxf(acc[nt][3] + by, 0.f);
            *(__half2*)&H1s[wm0 + gr][col]     = __floats2half2_rn(v0, v1);
            *(__half2*)&H1s[wm0 + gr + 8][col] = __floats2half2_rn(v2, v3);
        }
    }
    __syncthreads();

    // ---- stage B: K=512 streamed, out 32x256 -> H2s (relu) ----
    stage_stream<256, 264>(H1s, Wc, W1h, bb1, H2s);
    __syncthreads();

    // ---- stage C: K=256, out 32x64 -> P[:,0:64] (no relu) ----
    {
        float acc[2][4];
        #pragma unroll
        for (int nt = 0; nt < 2; nt++)
            #pragma unroll
            for (int e = 0; e < 4; e++)
                acc[nt][e] = 0.f;
        #pragma unroll 4
        for (int kk = 0; kk < 256; kk += 16) {
            uint32_t af[4];
            ldm_x4(af, smem_u32(&H2s[wm0 + lrow][kk + lkof]));
            #pragma unroll
            for (int nt = 0; nt < 2; nt++) {
                int n = wng * 16 + nt * 8 + gr;
                uint32_t b0 = *(const uint32_t*)&W2s[n][kk + 2 * qr];
                uint32_t b1 = *(const uint32_t*)&W2s[n][kk + 2 * qr + 8];
                mma_f16(acc[nt], af[0], af[1], af[2], af[3], b0, b1);
            }
        }
        float* P = g_scratch + OFF_P;
        #pragma unroll
        for (int nt = 0; nt < 2; nt++) {
            int col = wng * 16 + nt * 8 + 2 * qr;
            float bx = bb2[col], by = bb2[col + 1];
            float2 v0 = { acc[nt][0] + bx, acc[nt][1] + by };
            float2 v1 = { acc[nt][2] + bx, acc[nt][3] + by };
            *(float2*)&P[(size_t)(m0 + wm0 + gr) * PDIM + col]     = v0;
            *(float2*)&P[(size_t)(m0 + wm0 + gr + 8) * PDIM + col] = v1;
        }
    }
}

// ---------------------------------------------------------------------------
// Top MLP megakernel: 32 batch rows / CTA, grid 128.
//   A: T1 = relu(P @ TW0^T + tb0)     (K=512 streamed cp.async)
//   B: T2 = relu(T1 @ TW1^T + tb1)    (K=512 streamed cp.async)
//   C: out = T2 . tw2 + tb2           (SIMT dot, 8 threads/row)
// ---------------------------------------------------------------------------
#define TOP_SMEM 157184
__global__ __launch_bounds__(256)
void top_mlp(const __half* __restrict__ TW0h,
             const __half* __restrict__ TW1h,
             const float* __restrict__ tb0,
             const float* __restrict__ tb1,
             const float* __restrict__ tw2,
             const float* __restrict__ tb2,
             float* __restrict__ out)
{
    extern __shared__ __align__(16) char smem[];
    __half (*Xs)[520]  = (__half(*)[520])(smem + 0);       // 33280 B
    __half (*H1s)[520] = (__half(*)[520])(smem + 33280);   // 33280 B
    __half (*Wc)[72]   = (__half(*)[72] )(smem + 66560);   // 73728 B (4 bufs)
    __half (*H2s)[264] = (__half(*)[264])(smem + 140288);  // 16896 B

    const int tid = threadIdx.x;
    const int m0  = blockIdx.x * 32;

    // load P rows -> fp16
    const float* Pr = g_scratch + OFF_P + (size_t)m0 * PDIM;
    #pragma unroll
    for (int j = 0; j < 16; j++) {
        int f = tid + j * 256, r = f >> 7, cq = f & 127;
        float4 v = *(const float4*)&Pr[(size_t)r * PDIM + cq * 4];
        *(__half2*)&Xs[r][cq * 4]     = __floats2half2_rn(v.x, v.y);
        *(__half2*)&Xs[r][cq * 4 + 2] = __floats2half2_rn(v.z, v.w);
    }
    __syncthreads();

    stage_stream<512, 520>(Xs, Wc, TW0h, tb0, H1s);
    __syncthreads();
    stage_stream<256, 264>(H1s, Wc, TW1h, tb1, H2s);
    __syncthreads();

    // final dot: 8 threads per row
    {
        int r = tid >> 3, part = tid & 7;
        float s = 0.f;
        #pragma unroll
        for (int c = 0; c < 32; c++) {
            int col = part * 32 + c;
            s += __half2float(H2s[r][col]) * tw2[col];
        }
        s += __shfl_xor_sync(0xffffffffu, s, 1);
        s += __shfl_xor_sync(0xffffffffu, s, 2);
        s += __shfl_xor_sync(0xffffffffu, s, 4);
        if (part == 0) out[m0 + r] = s + tb2[0];
    }
}

// ---------------------------------------------------------------------------
// Interaction kernel. One warp per batch row; x_bot already in P[b][0:64].
// ---------------------------------------------------------------------------
#define IPAD 28

__global__ __launch_bounds__(128)
void interact_kernel(const int* __restrict__ sidx,
                     const float* __restrict__ emb)
{
    __shared__ __align__(16) float Tt[4][EMBD][IPAD];

    const int w    = threadIdx.x >> 5;
    const int lane = threadIdx.x & 31;
    const int b    = blockIdx.x * 4 + w;

    float* prow = g_scratch + OFF_P + (size_t)b * PDIM;
    float (*T)[IPAD] = Tt[w];

    const float* srcs[NI];
    srcs[0] = prow;
    #pragma unroll
    for (int r = 1; r < NI; r++) {
        int ix = sidx[(size_t)(r - 1) * BATCH + b];
        ix = ix < 0 ? 0 : (ix >= VOCAB ? VOCAB - 1 : ix);
        srcs[r] = emb + ((size_t)(r - 1) * VOCAB + (size_t)ix) * EMBD;
    }
    float2 vbuf[NI];
    #pragma unroll
    for (int r = 0; r < NI; r++)
        vbuf[r] = ((const float2*)srcs[r])[lane];
    #pragma unroll
    for (int r = 0; r < NI; r++) {
        T[2*lane    ][r] = vbuf[r].x;
        T[2*lane + 1][r] = vbuf[r].y;
    }
    __syncwarp();

    if (lane < 28) {
        int ti = 0;
        while ((ti + 1) * (ti + 2) / 2 <= lane) ti++;
        int tj = lane - ti * (ti + 1) / 2;

        float acc[4][4];
        #pragma unroll
        for (int a = 0; a < 4; a++)
            #pragma unroll
            for (int c = 0; c < 4; c++)
                acc[a][c] = 0.f;

        #pragma unroll 8
        for (int k = 0; k < EMBD; k++) {
            float4 av = *(const float4*)&T[k][4*ti];
            float4 bv = *(const float4*)&T[k][4*tj];
            float ra[4] = {av.x, av.y, av.z, av.w};
            float rb[4] = {bv.x, bv.y, bv.z, bv.w};
            #pragma unroll
            for (int a = 0; a < 4; a++)
                #pragma unroll
                for (int c = 0; c < 4; c++)
                    acc[a][c] += ra[a] * rb[c];
        }

        #pragma unroll
        for (int a = 0; a < 4; a++) {
            int i = 4*ti + a;
            #pragma unroll
            for (int c = 0; c < 4; c++) {
                int j = 4*tj + c;
                if (i < NI && j < i)
                    prow[EMBD + i*(i-1)/2 + j] = acc[a][c];
            }
        }
    }
}

// ---------------------------------------------------------------------------
// Launch sequence
// ---------------------------------------------------------------------------
extern "C" void kernel_launch(void* const* d_in, const int* in_sizes, int n_in,
                              void* d_out, int out_size)
{
    const float* dense_x = (const float*)d_in[0];
    const int*   sidx    = (const int*)d_in[1];
    const float* emb     = (const float*)d_in[2];
    const float* bw0 = (const float*)d_in[3];
    const float* bb0 = (const float*)d_in[4];
    const float* bw1 = (const float*)d_in[5];
    const float* bb1 = (const float*)d_in[6];
    const float* bw2 = (const float*)d_in[7];
    const float* bb2 = (const float*)d_in[8];
    const float* tw0 = (const float*)d_in[9];
    const float* tb0 = (const float*)d_in[10];
    const float* tw1 = (const float*)d_in[11];
    const float* tb1 = (const float*)d_in[12];
    const float* tw2 = (const float*)d_in[13];
    const float* tb2 = (const float*)d_in[14];
    float* out = (float*)d_out;

    __half* wh;
    cudaGetSymbolAddress((void**)&wh, g_wh);

    cudaFuncSetAttribute(bottom_mlp, cudaFuncAttributeMaxDynamicSharedMemorySize, BOT_SMEM);
    cudaFuncSetAttribute(top_mlp,    cudaFuncAttributeMaxDynamicSharedMemorySize, TOP_SMEM);

    prep_kernel<<<256, 256>>>(bw0, bw1, bw2, tw0, tw1);

    bottom_mlp<<<BATCH/32, 256, BOT_SMEM>>>(dense_x, wh + HW0, wh + HW1, wh + HW2,
                                            bb0, bb1, bb2);

    interact_kernel<<<BATCH/4, 128>>>(sidx, emb);

    top_mlp<<<BATCH/32, 256, TOP_SMEM>>>(wh + HTW0, wh + HTW1,
                                         tb0, tb1, tw2, tb2, out);
}

// round 10
// speedup vs baseline: 5.1265x; 1.0015x over previous
#include <cuda_runtime.h>
#include <cuda_fp16.h>
#include <cstdint>
#include <math.h>

// ---------------------------------------------------------------------------
// DLRM forward, 4 launches:
//   prep -> bottom_mlp (fused 3-layer) -> interact -> top_mlp (fused 3-layer)
// GEMMs: mma.sync m16n8k16 fp16 (fp32 accum). Weight streaming via cp.async
// 4-buffer pipeline (2 chunks in flight). 512 threads / 16 warps per CTA.
// ---------------------------------------------------------------------------

#define BATCH   4096
#define MDEN    13
#define NI      27
#define EMBD    64
#define VOCAB   100000
#define TOPIN   415
#define PDIM    512

#define OFF_P    0
#define SCRATCH_TOTAL (BATCH*PDIM)
__device__ __align__(16) float g_scratch[SCRATCH_TOTAL];

// fp16 weights
#define HW0   0                     // [512,32]  (bw0 zero-padded 13->32)
#define HW1   (HW0  + 512*32)       // [256,512]
#define HW2   (HW1  + 256*512)      // [64,256]
#define HTW0  (HW2  + 64*256)       // [512,512] (tw0 zero-padded 415->512)
#define HTW1  (HTW0 + 512*512)      // [256,512]
#define HTOTAL (HTW1 + 256*512)
__device__ __align__(16) __half g_wh[HTOTAL];

__device__ __forceinline__ uint32_t smem_u32(const void* p) {
    uint32_t a;
    asm("{ .reg .u64 t; cvta.to.shared.u64 t, %1; cvt.u32.u64 %0, t; }"
        : "=r"(a) : "l"(p));
    return a;
}
__device__ __forceinline__ void mma_f16(float* c, uint32_t a0, uint32_t a1,
                                        uint32_t a2, uint32_t a3,
                                        uint32_t b0, uint32_t b1) {
    asm volatile(
        "mma.sync.aligned.m16n8k16.row.col.f32.f16.f16.f32 "
        "{%0,%1,%2,%3}, {%4,%5,%6,%7}, {%8,%9}, {%0,%1,%2,%3};"
        : "+f"(c[0]), "+f"(c[1]), "+f"(c[2]), "+f"(c[3])
        : "r"(a0), "r"(a1), "r"(a2), "r"(a3), "r"(b0), "r"(b1));
}
__device__ __forceinline__ void ldm_x4(uint32_t* r, uint32_t addr) {
    asm volatile("ldmatrix.sync.aligned.m8n8.x4.shared.b16 {%0,%1,%2,%3}, [%4];"
                 : "=r"(r[0]), "=r"(r[1]), "=r"(r[2]), "=r"(r[3]) : "r"(addr));
}
__device__ __forceinline__ void cp16(uint32_t saddr, const void* g) {
    asm volatile("cp.async.cg.shared.global [%0], [%1], 16;" :: "r"(saddr), "l"(g));
}
#define CP_COMMIT() asm volatile("cp.async.commit_group;" ::: "memory")

// ---------------------------------------------------------------------------
// Prep
// ---------------------------------------------------------------------------
__global__ void prep_kernel(const float* __restrict__ bw0,
                            const float* __restrict__ bw1,
                            const float* __restrict__ bw2,
                            const float* __restrict__ tw0,
                            const float* __restrict__ tw1)
{
    int tid = blockIdx.x * blockDim.x + threadIdx.x;
    int stride = gridDim.x * blockDim.x;

    for (int i = tid; i < 512 * 32; i += stride) {
        int r = i >> 5, c = i & 31;
        g_wh[HW0 + i] = __float2half_rn((c < MDEN) ? bw0[r * MDEN + c] : 0.f);
    }
    for (int i = tid; i < 256 * 512; i += stride)
        g_wh[HW1 + i] = __float2half_rn(bw1[i]);
    for (int i = tid; i < 64 * 256; i += stride)
        g_wh[HW2 + i] = __float2half_rn(bw2[i]);
    for (int i = tid; i < 512 * 512; i += stride) {
        int r = i >> 9, c = i & 511;
        g_wh[HTW0 + i] = __float2half_rn((c < TOPIN) ? tw0[r * TOPIN + c] : 0.f);
    }
    for (int i = tid; i < 256 * 512; i += stride)
        g_wh[HTW1 + i] = __float2half_rn(tw1[i]);
    for (int i = tid; i < BATCH * (PDIM - TOPIN); i += stride) {
        int r = i / (PDIM - TOPIN), c = TOPIN + i % (PDIM - TOPIN);
        g_scratch[OFF_P + (size_t)r * PDIM + c] = 0.f;
    }
}

// ---------------------------------------------------------------------------
// Streamed-W stage (512 threads / 16 warps):
//   Ds[32][NOUT] = relu( As[32][512] @ Wg[NOUT,512]^T + bias )
// W streamed in [128 n x 64 k] fp16 chunks via cp.async, 4 buffers, depth 2.
// Warp map: wm0 = (wid>>3)*16 (m16 group), wng = wid&7 (n16 group), nt=2.
// ---------------------------------------------------------------------------
template<int NOUT, int DSTRIDE>
__device__ __forceinline__ void stage_stream(
    const __half (*As)[520],
    __half (*Wc)[72],                 // [4*128][72]
    const __half* __restrict__ Wg,    // [NOUT, 512]
    const float* __restrict__ bias,
    __half (*Ds)[DSTRIDE])
{
    const int tid  = threadIdx.x;
    const int lane = tid & 31, wid = tid >> 5;
    const int qr   = lane & 3, gr = lane >> 2;
    const int wm0  = (wid >> 3) * 16, wng = wid & 7;
    const int lrow = lane & 15, lkof = (lane >> 4) << 3;
    constexpr int NC = (NOUT / 128) * 8;

    auto issue = [&](int g) {
        int nb = g >> 3, kc = g & 7;
        const __half* src = Wg + (size_t)(nb * 128) * 512 + kc * 64;
        __half (*buf)[72] = Wc + (g & 3) * 128;
        #pragma unroll
        for (int j = 0; j < 2; j++) {
            int f = tid + j * 512, r = f >> 3, c = (f & 7) * 8;
            cp16(smem_u32(&buf[r][c]), src + (size_t)r * 512 + c);
        }
        CP_COMMIT();
    };

    issue(0);
    if (NC > 1) issue(1);

    float acc[2][4];
    #pragma unroll
    for (int nt = 0; nt < 2; nt++)
        #pragma unroll
        for (int e = 0; e < 4; e++)
            acc[nt][e] = 0.f;

    #pragma unroll 1
    for (int g = 0; g < NC; g++) {
        if (g + 2 < NC) issue(g + 2);

        int rem = NC - 1 - g;
        if (rem >= 2)      asm volatile("cp.async.wait_group 2;" ::: "memory");
        else if (rem == 1) asm volatile("cp.async.wait_group 1;" ::: "memory");
        else               asm volatile("cp.async.wait_group 0;" ::: "memory");
        __syncthreads();

        const __half (*Wb)[72] = Wc + (g & 3) * 128;
        const int kc = g & 7;

        #pragma unroll
        for (int kk = 0; kk < 64; kk += 16) {
            uint32_t af[4];
            ldm_x4(af, smem_u32(&As[wm0 + lrow][kc * 64 + kk + lkof]));
            #pragma unroll
            for (int nt = 0; nt < 2; nt++) {
                int n = wng * 16 + nt * 8 + gr;
                uint32_t b0 = *(const uint32_t*)&Wb[n][kk + 2 * qr];
                uint32_t b1 = *(const uint32_t*)&Wb[n][kk + 2 * qr + 8];
                mma_f16(acc[nt], af[0], af[1], af[2], af[3], b0, b1);
            }
        }

        if (kc == 7) {
            int nb = g >> 3;
            #pragma unroll
            for (int nt = 0; nt < 2; nt++) {
                int col = nb * 128 + wng * 16 + nt * 8 + 2 * qr;
                float bx = bias[col], by = bias[col + 1];
                float v0 = fmaxf(acc[nt][0] + bx, 0.f), v1 = fmaxf(acc[nt][1] + by, 0.f);
                float v2 = fmaxf(acc[nt][2] + bx, 0.f), v3 = fmaxf(acc[nt][3] + by, 0.f);
                *(__half2*)&Ds[wm0 + gr][col]     = __floats2half2_rn(v0, v1);
                *(__half2*)&Ds[wm0 + gr + 8][col] = __floats2half2_rn(v2, v3);
                #pragma unroll
                for (int e = 0; e < 4; e++) acc[nt][e] = 0.f;
            }
        }
    }
}

// ---------------------------------------------------------------------------
// Bottom MLP megakernel: 32 batch rows / CTA, grid 128, 512 threads.
// ---------------------------------------------------------------------------
#define BOT_SMEM 201216
__global__ __launch_bounds__(512)
void bottom_mlp(const float* __restrict__ dense_x,
                const __half* __restrict__ W0h,
                const __half* __restrict__ W1h,
                const __half* __restrict__ W2h,
                const float* __restrict__ bb0,
                const float* __restrict__ bb1,
                const float* __restrict__ bb2)
{
    extern __shared__ __align__(16) char smem[];
    __half (*Xs)[40]   = (__half(*)[40] )(smem + 0);       //  2560 B
    __half (*W0s)[40]  = (__half(*)[40] )(smem + 2560);    // 40960 B
    __half (*H1s)[520] = (__half(*)[520])(smem + 43520);   // 33280 B
    __half (*Wc)[72]   = (__half(*)[72] )(smem + 76800);   // 73728 B (4 bufs)
    __half (*H2s)[264] = (__half(*)[264])(smem + 150528);  // 16896 B
    __half (*W2s)[264] = (__half(*)[264])(smem + 167424);  // 33792 B

    const int tid  = threadIdx.x;
    const int lane = tid & 31, wid = tid >> 5;
    const int qr   = lane & 3, gr = lane >> 2;
    const int wm0  = (wid >> 3) * 16, wng = wid & 7;
    const int lrow = lane & 15, lkof = (lane >> 4) << 3;
    const int m0   = blockIdx.x * 32;

    // ---- loads ----
    for (int i = tid; i < 32 * MDEN; i += 512) {
        int r = i / MDEN, c = i % MDEN;
        Xs[r][c] = __float2half_rn(dense_x[(size_t)(m0 + r) * MDEN + c]);
    }
    for (int i = tid; i < 32 * (32 - MDEN); i += 512) {
        int r = i / (32 - MDEN), c = MDEN + i % (32 - MDEN);
        Xs[r][c] = __float2half_rn(0.f);
    }
    #pragma unroll
    for (int j = 0; j < 4; j++) {                    // W0s: 512x32 halves
        int f = tid + j * 512, r = f >> 2, c = (f & 3) * 8;
        *(uint4*)&W0s[r][c] = *(const uint4*)&W0h[r * 32 + c];
    }
    #pragma unroll
    for (int j = 0; j < 4; j++) {                    // W2s: 64x256 halves
        int f = tid + j * 512, r = f >> 5, c = (f & 31) * 8;
        *(uint4*)&W2s[r][c] = *(const uint4*)&W2h[r * 256 + c];
    }
    __syncthreads();

    // ---- stage A: K=32, out 32x512 -> H1s (relu) ----
    #pragma unroll 1
    for (int nb = 0; nb < 4; nb++) {
        float acc[2][4];
        #pragma unroll
        for (int nt = 0; nt < 2; nt++)
            #pragma unroll
            for (int e = 0; e < 4; e++)
                acc[nt][e] = 0.f;
        #pragma unroll
        for (int kk = 0; kk < 32; kk += 16) {
            uint32_t af[4];
            ldm_x4(af, smem_u32(&Xs[wm0 + lrow][kk + lkof]));
            #pragma unroll
            for (int nt = 0; nt < 2; nt++) {
                int n = nb * 128 + wng * 16 + nt * 8 + gr;
                uint32_t b0 = *(const uint32_t*)&W0s[n][kk + 2 * qr];
                uint32_t b1 = *(const uint32_t*)&W0s[n][kk + 2 * qr + 8];
                mma_f16(acc[nt], af[0], af[1], af[2], af[3], b0, b1);
            }
        }
        #pragma unroll
        for (int nt = 0; nt < 2; nt++) {
            int col = nb * 128 + wng * 16 + nt * 8 + 2 * qr;
            float bx = bb0[col], by = bb0[col + 1];
            float v0 = fmaxf(acc[nt][0] + bx, 0.f), v1 = fmaxf(acc[nt][1] + by, 0.f);
            float v2 = fmaxf(acc[nt][2] + bx, 0.f), v3 = fmaxf(acc[nt][3] + by, 0.f);
            *(__half2*)&H1s[wm0 + gr][col]     = __floats2half2_rn(v0, v1);
            *(__half2*)&H1s[wm0 + gr + 8][col] = __floats2half2_rn(v2, v3);
        }
    }
    __syncthreads();

    // ---- stage B: K=512 streamed, out 32x256 -> H2s (relu) ----
    stage_stream<256, 264>(H1s, Wc, W1h, bb1, H2s);
    __syncthreads();

    // ---- stage C: K=256, out 32x64 -> P[:,0:64] (no relu) ----
    {
        float acc[4];
        #pragma unroll
        for (int e = 0; e < 4; e++) acc[e] = 0.f;
        const int n = wng * 8 + gr;
        #pragma unroll 4
        for (int kk = 0; kk < 256; kk += 16) {
            uint32_t af[4];
            ldm_x4(af, smem_u32(&H2s[wm0 + lrow][kk + lkof]));
            uint32_t b0 = *(const uint32_t*)&W2s[n][kk + 2 * qr];
            uint32_t b1 = *(const uint32_t*)&W2s[n][kk + 2 * qr + 8];
            mma_f16(acc, af[0], af[1], af[2], af[3], b0, b1);
        }
        float* P = g_scratch + OFF_P;
        int col = wng * 8 + 2 * qr;
        float bx = bb2[col], by = bb2[col + 1];
        float2 v0 = { acc[0] + bx, acc[1] + by };
        float2 v1 = { acc[2] + bx, acc[3] + by };
        *(float2*)&P[(size_t)(m0 + wm0 + gr) * PDIM + col]     = v0;
        *(float2*)&P[(size_t)(m0 + wm0 + gr + 8) * PDIM + col] = v1;
    }
}

// ---------------------------------------------------------------------------
// Top MLP megakernel: 32 batch rows / CTA, grid 128, 512 threads.
// ---------------------------------------------------------------------------
#define TOP_SMEM 157184
__global__ __launch_bounds__(512)
void top_mlp(const __half* __restrict__ TW0h,
             const __half* __restrict__ TW1h,
             const float* __restrict__ tb0,
             const float* __restrict__ tb1,
             const float* __restrict__ tw2,
             const float* __restrict__ tb2,
             float* __restrict__ out)
{
    extern __shared__ __align__(16) char smem[];
    __half (*Xs)[520]  = (__half(*)[520])(smem + 0);       // 33280 B
    __half (*H1s)[520] = (__half(*)[520])(smem + 33280);   // 33280 B
    __half (*Wc)[72]   = (__half(*)[72] )(smem + 66560);   // 73728 B (4 bufs)
    __half (*H2s)[264] = (__half(*)[264])(smem + 140288);  // 16896 B

    const int tid = threadIdx.x;
    const int m0  = blockIdx.x * 32;

    // load P rows -> fp16
    const float* Pr = g_scratch + OFF_P + (size_t)m0 * PDIM;
    #pragma unroll
    for (int j = 0; j < 8; j++) {
        int f = tid + j * 512, r = f >> 7, cq = f & 127;
        float4 v = *(const float4*)&Pr[(size_t)r * PDIM + cq * 4];
        *(__half2*)&Xs[r][cq * 4]     = __floats2half2_rn(v.x, v.y);
        *(__half2*)&Xs[r][cq * 4 + 2] = __floats2half2_rn(v.z, v.w);
    }
    __syncthreads();

    stage_stream<512, 520>(Xs, Wc, TW0h, tb0, H1s);
    __syncthreads();
    stage_stream<256, 264>(H1s, Wc, TW1h, tb1, H2s);
    __syncthreads();

    // final dot: 16 threads per row
    {
        int r = tid >> 4, part = tid & 15;
        float s = 0.f;
        #pragma unroll
        for (int c = 0; c < 16; c++) {
            int col = part * 16 + c;
            s += __half2float(H2s[r][col]) * tw2[col];
        }
        s += __shfl_xor_sync(0xffffffffu, s, 1);
        s += __shfl_xor_sync(0xffffffffu, s, 2);
        s += __shfl_xor_sync(0xffffffffu, s, 4);
        s += __shfl_xor_sync(0xffffffffu, s, 8);
        if (part == 0) out[m0 + r] = s + tb2[0];
    }
}

// ---------------------------------------------------------------------------
// Interaction kernel. One warp per batch row; x_bot already in P[b][0:64].
// ---------------------------------------------------------------------------
#define IPAD 28

__global__ __launch_bounds__(128)
void interact_kernel(const int* __restrict__ sidx,
                     const float* __restrict__ emb)
{
    __shared__ __align__(16) float Tt[4][EMBD][IPAD];

    const int w    = threadIdx.x >> 5;
    const int lane = threadIdx.x & 31;
    const int b    = blockIdx.x * 4 + w;

    float* prow = g_scratch + OFF_P + (size_t)b * PDIM;
    float (*T)[IPAD] = Tt[w];

    const float* srcs[NI];
    srcs[0] = prow;
    #pragma unroll
    for (int r = 1; r < NI; r++) {
        int ix = sidx[(size_t)(r - 1) * BATCH + b];
        ix = ix < 0 ? 0 : (ix >= VOCAB ? VOCAB - 1 : ix);
        srcs[r] = emb + ((size_t)(r - 1) * VOCAB + (size_t)ix) * EMBD;
    }
    float2 vbuf[NI];
    #pragma unroll
    for (int r = 0; r < NI; r++)
        vbuf[r] = ((const float2*)srcs[r])[lane];
    #pragma unroll
    for (int r = 0; r < NI; r++) {
        T[2*lane    ][r] = vbuf[r].x;
        T[2*lane + 1][r] = vbuf[r].y;
    }
    __syncwarp();

    if (lane < 28) {
        int ti = 0;
        while ((ti + 1) * (ti + 2) / 2 <= lane) ti++;
        int tj = lane - ti * (ti + 1) / 2;

        float acc[4][4];
        #pragma unroll
        for (int a = 0; a < 4; a++)
            #pragma unroll
            for (int c = 0; c < 4; c++)
                acc[a][c] = 0.f;

        #pragma unroll 8
        for (int k = 0; k < EMBD; k++) {
            float4 av = *(const float4*)&T[k][4*ti];
            float4 bv = *(const float4*)&T[k][4*tj];
            float ra[4] = {av.x, av.y, av.z, av.w};
            float rb[4] = {bv.x, bv.y, bv.z, bv.w};
            #pragma unroll
            for (int a = 0; a < 4; a++)
                #pragma unroll
                for (int c = 0; c < 4; c++)
                    acc[a][c] += ra[a] * rb[c];
        }

        #pragma unroll
        for (int a = 0; a < 4; a++) {
            int i = 4*ti + a;
            #pragma unroll
            for (int c = 0; c < 4; c++) {
                int j = 4*tj + c;
                if (i < NI && j < i)
                    prow[EMBD + i*(i-1)/2 + j] = acc[a][c];
            }
        }
    }
}

// ---------------------------------------------------------------------------
// Launch sequence
// ---------------------------------------------------------------------------
extern "C" void kernel_launch(void* const* d_in, const int* in_sizes, int n_in,
                              void* d_out, int out_size)
{
    const float* dense_x = (const float*)d_in[0];
    const int*   sidx    = (const int*)d_in[1];
    const float* emb     = (const float*)d_in[2];
    const float* bw0 = (const float*)d_in[3];
    const float* bb0 = (const float*)d_in[4];
    const float* bw1 = (const float*)d_in[5];
    const float* bb1 = (const float*)d_in[6];
    const float* bw2 = (const float*)d_in[7];
    const float* bb2 = (const float*)d_in[8];
    const float* tw0 = (const float*)d_in[9];
    const float* tb0 = (const float*)d_in[10];
    const float* tw1 = (const float*)d_in[11];
    const float* tb1 = (const float*)d_in[12];
    const float* tw2 = (const float*)d_in[13];
    const float* tb2 = (const float*)d_in[14];
    float* out = (float*)d_out;

    __half* wh;
    cudaGetSymbolAddress((void**)&wh, g_wh);

    cudaFuncSetAttribute(bottom_mlp, cudaFuncAttributeMaxDynamicSharedMemorySize, BOT_SMEM);
    cudaFuncSetAttribute(top_mlp,    cudaFuncAttributeMaxDynamicSharedMemorySize, TOP_SMEM);

    prep_kernel<<<256, 256>>>(bw0, bw1, bw2, tw0, tw1);

    bottom_mlp<<<BATCH/32, 512, BOT_SMEM>>>(dense_x, wh + HW0, wh + HW1, wh + HW2,
                                            bb0, bb1, bb2);

    interact_kernel<<<BATCH/4, 128>>>(sidx, emb);

    top_mlp<<<BATCH/32, 512, TOP_SMEM>>>(wh + HTW0, wh + HTW1,
                                         tb0, tb1, tw2, tb2, out);
}